// round 1
// baseline (speedup 1.0000x reference)
#include <cuda_runtime.h>
#include <cuda_bf16.h>
#include <math.h>

// ---------------------------------------------------------------------------
// Problem constants
// ---------------------------------------------------------------------------
#define BB 4
#define NN 2304
#define CC 256
#define HH 8
#define DD 32
#define KVLD 512
#define SCALE 0.17677669529663687f   // 32^-0.5
#define ROWS (BB*NN)                 // 9216
#define HDS 48
#define OUT_PER_PATH (BB*CC*96*96)   // 9437184

// ---------------------------------------------------------------------------
// Scratch (static device globals; allocation at module load, graph-safe)
// ---------------------------------------------------------------------------
__device__ __align__(16) float g_q1[ROWS*CC];
__device__ __align__(16) float g_kv1[ROWS*KVLD];
__device__ __align__(16) float g_q2[ROWS*CC];
__device__ __align__(16) float g_kv2[ROWS*KVLD];
__device__ __align__(16) float g_o1[ROWS*CC];
__device__ __align__(16) float g_o2[ROWS*CC];
__device__ __align__(16) float g_z1[ROWS*CC];
__device__ __align__(16) float g_z2[ROWS*CC];
__device__ __align__(16) float g_y1[ROWS*CC];
__device__ __align__(16) float g_y2[ROWS*CC];

// ---------------------------------------------------------------------------
// SGEMM (NT): C[i,j] = act( sum_k A[i,k] * W[j,k] + bias[j] )
// A: [M,K] row-major, W: [Nout,K] row-major (torch Linear weight), C: [M,Nout]
// Tiles 128x128x8, 256 threads, 8x8 per thread.
// Requires M%128==0, Nout%128==0, K%8==0 (true for all calls here).
// ---------------------------------------------------------------------------
__global__ __launch_bounds__(256) void cp_sgemm_nt(
    const float* __restrict__ A, const float* __restrict__ W,
    const float* __restrict__ bias, float* __restrict__ C,
    int M, int Nout, int K, int relu)
{
    __shared__ float As[8][128];
    __shared__ float Bs[8][128];

    const int tid = threadIdx.x;
    const int tx = tid & 15;        // 0..15 -> col group
    const int ty = tid >> 4;        // 0..15 -> row group
    const int row0 = blockIdx.y * 128;
    const int col0 = blockIdx.x * 128;

    const int lrow = tid >> 1;      // 0..127
    const int lk4  = (tid & 1) * 4; // 0 or 4

    const float* Aptr = A + (size_t)(row0 + lrow) * K + lk4;
    const float* Wptr = W + (size_t)(col0 + lrow) * K + lk4;

    float acc[8][8];
    #pragma unroll
    for (int i = 0; i < 8; i++)
        #pragma unroll
        for (int j = 0; j < 8; j++) acc[i][j] = 0.f;

    for (int k0 = 0; k0 < K; k0 += 8) {
        float4 av = *(const float4*)(Aptr + k0);
        float4 wv = *(const float4*)(Wptr + k0);
        As[lk4+0][lrow] = av.x; As[lk4+1][lrow] = av.y;
        As[lk4+2][lrow] = av.z; As[lk4+3][lrow] = av.w;
        Bs[lk4+0][lrow] = wv.x; Bs[lk4+1][lrow] = wv.y;
        Bs[lk4+2][lrow] = wv.z; Bs[lk4+3][lrow] = wv.w;
        __syncthreads();

        #pragma unroll
        for (int k = 0; k < 8; k++) {
            float a[8], b[8];
            #pragma unroll
            for (int r = 0; r < 8; r++) a[r] = As[k][ty*8 + r];
            #pragma unroll
            for (int r = 0; r < 8; r++) b[r] = Bs[k][tx*8 + r];
            #pragma unroll
            for (int i = 0; i < 8; i++)
                #pragma unroll
                for (int j = 0; j < 8; j++)
                    acc[i][j] += a[i] * b[j];
        }
        __syncthreads();
    }

    #pragma unroll
    for (int i = 0; i < 8; i++) {
        int r = row0 + ty*8 + i;
        #pragma unroll
        for (int j = 0; j < 8; j++) {
            int c = col0 + tx*8 + j;
            float v = acc[i][j];
            if (bias) v += bias[c];
            if (relu) v = fmaxf(v, 0.f);
            C[(size_t)r * Nout + c] = v;
        }
    }
}

// ---------------------------------------------------------------------------
// Flash attention, both cross paths in one grid.
// Grid: (N/128, H, B*2).  One thread per query row; D=32 in registers.
// K/V streamed in 32-key tiles through shared memory.
// Q: [B*N, 256] col = h*32+d.  KV: [B*N, 512] k at +0, v at +256.
// ---------------------------------------------------------------------------
__global__ __launch_bounds__(128) void cp_flash(
    const float* __restrict__ Q1, const float* __restrict__ KV2,
    const float* __restrict__ Beta12, float* __restrict__ O1,
    const float* __restrict__ Q2, const float* __restrict__ KV1,
    const float* __restrict__ Beta21, float* __restrict__ O2)
{
    const int i = blockIdx.x * 128 + threadIdx.x;   // query token
    const int h = blockIdx.y;
    const int z = blockIdx.z;
    const int b = z & 3;
    const int path = z >> 2;

    const float* Q    = path ? Q2     : Q1;
    const float* KV   = path ? KV1    : KV2;
    const float* Beta = path ? Beta21 : Beta12;
    float*       O    = path ? O2     : O1;

    __shared__ float ks[32][32];
    __shared__ float vs[32][32];

    float qr[32];
    const float* qp = Q + ((size_t)b * NN + i) * CC + h * DD;
    #pragma unroll
    for (int d = 0; d < 32; d++) qr[d] = qp[d];

    const float betav = Beta[h];
    float m = -1e30f, l = 0.f;
    float acc[32];
    #pragma unroll
    for (int d = 0; d < 32; d++) acc[d] = 0.f;

    const float* kvb = KV + ((size_t)b * NN) * KVLD + h * DD;
    const int tid = threadIdx.x;

    for (int t = 0; t < NN / 32; t++) {
        #pragma unroll
        for (int it = 0; it < 8; it++) {
            int idx = it * 128 + tid;        // 0..1023
            int j = idx >> 5, d = idx & 31;
            const float* src = kvb + (size_t)(t * 32 + j) * KVLD + d;
            ks[j][d] = src[0];
            vs[j][d] = src[256];
        }
        __syncthreads();

        float s[32];
        float tmax = -1e30f;
        #pragma unroll 4
        for (int j = 0; j < 32; j++) {
            float a0 = 0.f, a1 = 0.f;
            #pragma unroll
            for (int d = 0; d < 32; d += 2) {
                a0 += qr[d]     * ks[j][d];
                a1 += qr[d + 1] * ks[j][d + 1];
            }
            float sv = (a0 + a1) * SCALE + betav;
            s[j] = sv;
            tmax = fmaxf(tmax, sv);
        }

        float mnew = fmaxf(m, tmax);
        float corr = __expf(m - mnew);
        l *= corr;
        #pragma unroll
        for (int d = 0; d < 32; d++) acc[d] *= corr;

        #pragma unroll 4
        for (int j = 0; j < 32; j++) {
            float p = __expf(s[j] - mnew);
            l += p;
            #pragma unroll
            for (int d = 0; d < 32; d++) acc[d] += p * vs[j][d];
        }
        m = mnew;
        __syncthreads();
    }

    const float inv = 1.f / l;
    float* op = O + ((size_t)b * NN + i) * CC + h * DD;
    #pragma unroll
    for (int d = 0; d < 32; d++) op[d] = acc[d] * inv;
}

// ---------------------------------------------------------------------------
// LayerNorm over C=256.  One block per row, 256 threads.
// ---------------------------------------------------------------------------
__global__ __launch_bounds__(256) void cp_layernorm(
    const float* __restrict__ Z, const float* __restrict__ g,
    const float* __restrict__ bta, float* __restrict__ Y)
{
    const int row = blockIdx.x;
    const int t = threadIdx.x;
    float v = Z[(size_t)row * CC + t];

    float s = v, q = v * v;
    #pragma unroll
    for (int o = 16; o > 0; o >>= 1) {
        s += __shfl_xor_sync(0xffffffffu, s, o);
        q += __shfl_xor_sync(0xffffffffu, q, o);
    }
    __shared__ float ssum[8], ssq[8];
    if ((t & 31) == 0) { ssum[t >> 5] = s; ssq[t >> 5] = q; }
    __syncthreads();
    __shared__ float smu, sinv;
    if (t == 0) {
        float ts = 0.f, tq = 0.f;
        #pragma unroll
        for (int w = 0; w < 8; w++) { ts += ssum[w]; tq += ssq[w]; }
        float mu = ts * (1.f / CC);
        float var = tq * (1.f / CC) - mu * mu;
        smu = mu;
        sinv = rsqrtf(var + 1e-5f);
    }
    __syncthreads();
    Y[(size_t)row * CC + t] = (v - smu) * sinv * g[t] + bta[t];
}

// ---------------------------------------------------------------------------
// Bilinear upsample x2, half-pixel, [B,N,C] (n=iy*48+ix) -> [B,C,96,96]
// ---------------------------------------------------------------------------
__global__ __launch_bounds__(256) void cp_upsample(
    const float* __restrict__ Y, float* __restrict__ out)
{
    int idx = blockIdx.x * blockDim.x + threadIdx.x;
    if (idx >= OUT_PER_PATH) return;
    int ox = idx % 96;
    int oy = (idx / 96) % 96;
    int c  = (idx / (96 * 96)) % CC;
    int b  = idx / (96 * 96 * CC);

    float sx = ox * 0.5f - 0.25f;
    float sy = oy * 0.5f - 0.25f;
    int x0 = (int)floorf(sx), y0 = (int)floorf(sy);
    float wx = sx - (float)x0, wy = sy - (float)y0;
    int x0c = max(x0, 0), x1c = min(x0 + 1, HDS - 1);
    int y0c = max(y0, 0), y1c = min(y0 + 1, HDS - 1);

    const float* Yb = Y + (size_t)b * NN * CC + c;
    float v00 = Yb[(size_t)(y0c * HDS + x0c) * CC];
    float v01 = Yb[(size_t)(y0c * HDS + x1c) * CC];
    float v10 = Yb[(size_t)(y1c * HDS + x0c) * CC];
    float v11 = Yb[(size_t)(y1c * HDS + x1c) * CC];

    out[idx] = (1.f - wy) * ((1.f - wx) * v00 + wx * v01)
             +        wy  * ((1.f - wx) * v10 + wx * v11);
}

// ---------------------------------------------------------------------------
// Launch
// ---------------------------------------------------------------------------
extern "C" void kernel_launch(void* const* d_in, const int* in_sizes, int n_in,
                              void* d_out, int out_size)
{
    const float* x1     = (const float*)d_in[0];
    const float* x2     = (const float*)d_in[1];
    const float* q1_w   = (const float*)d_in[2];
    const float* kv1_w  = (const float*)d_in[3];
    const float* q2_w   = (const float*)d_in[4];
    const float* kv2_w  = (const float*)d_in[5];
    const float* beta12 = (const float*)d_in[6];
    const float* beta21 = (const float*)d_in[7];
    const float* p1_w   = (const float*)d_in[8];
    const float* p1_b   = (const float*)d_in[9];
    const float* p2_w   = (const float*)d_in[10];
    const float* p2_b   = (const float*)d_in[11];
    const float* g1     = (const float*)d_in[12];
    const float* b1     = (const float*)d_in[13];
    const float* g2     = (const float*)d_in[14];
    const float* b2     = (const float*)d_in[15];
    float* out = (float*)d_out;

    float *q1, *kv1, *q2, *kv2, *o1, *o2, *z1, *z2, *y1, *y2;
    cudaGetSymbolAddress((void**)&q1,  g_q1);
    cudaGetSymbolAddress((void**)&kv1, g_kv1);
    cudaGetSymbolAddress((void**)&q2,  g_q2);
    cudaGetSymbolAddress((void**)&kv2, g_kv2);
    cudaGetSymbolAddress((void**)&o1,  g_o1);
    cudaGetSymbolAddress((void**)&o2,  g_o2);
    cudaGetSymbolAddress((void**)&z1,  g_z1);
    cudaGetSymbolAddress((void**)&z2,  g_z2);
    cudaGetSymbolAddress((void**)&y1,  g_y1);
    cudaGetSymbolAddress((void**)&y2,  g_y2);

    // Projections
    cp_sgemm_nt<<<dim3(CC/128, ROWS/128), 256>>>(x1, q1_w,  nullptr, q1,  ROWS, CC,   CC, 0);
    cp_sgemm_nt<<<dim3(KVLD/128, ROWS/128), 256>>>(x1, kv1_w, nullptr, kv1, ROWS, KVLD, CC, 0);
    cp_sgemm_nt<<<dim3(CC/128, ROWS/128), 256>>>(x2, q2_w,  nullptr, q2,  ROWS, CC,   CC, 0);
    cp_sgemm_nt<<<dim3(KVLD/128, ROWS/128), 256>>>(x2, kv2_w, nullptr, kv2, ROWS, KVLD, CC, 0);

    // Cross attention, both paths
    cp_flash<<<dim3(NN/128, HH, BB*2), 128>>>(q1, kv2, beta12, o1,
                                              q2, kv1, beta21, o2);

    // Output projection + bias + relu
    cp_sgemm_nt<<<dim3(CC/128, ROWS/128), 256>>>(o1, p1_w, p1_b, z1, ROWS, CC, CC, 1);
    cp_sgemm_nt<<<dim3(CC/128, ROWS/128), 256>>>(o2, p2_w, p2_b, z2, ROWS, CC, CC, 1);

    // LayerNorm
    cp_layernorm<<<ROWS, 256>>>(z1, g1, b1, y1);
    cp_layernorm<<<ROWS, 256>>>(z2, g2, b2, y2);

    // Bilinear upsample x2 -> output (y1 then y2)
    int ublocks = (OUT_PER_PATH + 255) / 256;
    cp_upsample<<<ublocks, 256>>>(y1, out);
    cp_upsample<<<ublocks, 256>>>(y2, out + OUT_PER_PATH);
}

// round 2
// speedup vs baseline: 1.2126x; 1.2126x over previous
#include <cuda_runtime.h>
#include <cuda_bf16.h>
#include <math.h>

// ---------------------------------------------------------------------------
// Problem constants
// ---------------------------------------------------------------------------
#define BB 4
#define NN 2304
#define CC 256
#define HH 8
#define DD 32
#define KVLD 512
#define SCALE 0.17677669529663687f   // 32^-0.5
#define ROWS (BB*NN)                 // 9216
#define HDS 48
#define OUT_PER_PATH (BB*CC*96*96)   // 9437184
#define TK 64                        // keys per shared tile

// ---------------------------------------------------------------------------
// Scratch (static device globals; allocation at module load, graph-safe)
// ---------------------------------------------------------------------------
__device__ __align__(16) float g_q1[ROWS*CC];
__device__ __align__(16) float g_kv1[ROWS*KVLD];
__device__ __align__(16) float g_q2[ROWS*CC];
__device__ __align__(16) float g_kv2[ROWS*KVLD];
__device__ __align__(16) float g_o1[ROWS*CC];
__device__ __align__(16) float g_o2[ROWS*CC];
__device__ __align__(16) float g_z1[ROWS*CC];
__device__ __align__(16) float g_z2[ROWS*CC];
__device__ __align__(16) float g_y1[ROWS*CC];
__device__ __align__(16) float g_y2[ROWS*CC];

// ---------------------------------------------------------------------------
// SGEMM (NT): C[i,j] = act( sum_k A[i,k] * W[j,k] + bias[j] )
// ---------------------------------------------------------------------------
__global__ __launch_bounds__(256) void cp_sgemm_nt(
    const float* __restrict__ A, const float* __restrict__ W,
    const float* __restrict__ bias, float* __restrict__ C,
    int M, int Nout, int K, int relu)
{
    __shared__ float As[8][128];
    __shared__ float Bs[8][128];

    const int tid = threadIdx.x;
    const int tx = tid & 15;
    const int ty = tid >> 4;
    const int row0 = blockIdx.y * 128;
    const int col0 = blockIdx.x * 128;

    const int lrow = tid >> 1;
    const int lk4  = (tid & 1) * 4;

    const float* Aptr = A + (size_t)(row0 + lrow) * K + lk4;
    const float* Wptr = W + (size_t)(col0 + lrow) * K + lk4;

    float acc[8][8];
    #pragma unroll
    for (int i = 0; i < 8; i++)
        #pragma unroll
        for (int j = 0; j < 8; j++) acc[i][j] = 0.f;

    for (int k0 = 0; k0 < K; k0 += 8) {
        float4 av = *(const float4*)(Aptr + k0);
        float4 wv = *(const float4*)(Wptr + k0);
        As[lk4+0][lrow] = av.x; As[lk4+1][lrow] = av.y;
        As[lk4+2][lrow] = av.z; As[lk4+3][lrow] = av.w;
        Bs[lk4+0][lrow] = wv.x; Bs[lk4+1][lrow] = wv.y;
        Bs[lk4+2][lrow] = wv.z; Bs[lk4+3][lrow] = wv.w;
        __syncthreads();

        #pragma unroll
        for (int k = 0; k < 8; k++) {
            float a[8], b[8];
            #pragma unroll
            for (int r = 0; r < 8; r++) a[r] = As[k][ty*8 + r];
            #pragma unroll
            for (int r = 0; r < 8; r++) b[r] = Bs[k][tx*8 + r];
            #pragma unroll
            for (int i = 0; i < 8; i++)
                #pragma unroll
                for (int j = 0; j < 8; j++)
                    acc[i][j] += a[i] * b[j];
        }
        __syncthreads();
    }

    #pragma unroll
    for (int i = 0; i < 8; i++) {
        int r = row0 + ty*8 + i;
        #pragma unroll
        for (int j = 0; j < 8; j++) {
            int c = col0 + tx*8 + j;
            float v = acc[i][j];
            if (bias) v += bias[c];
            if (relu) v = fmaxf(v, 0.f);
            C[(size_t)r * Nout + c] = v;
        }
    }
}

// ---------------------------------------------------------------------------
// Flash attention v2: 2 queries/thread, float4 LDS, exp-immediate (no running
// max: logits bounded << fp32 range; softmax is shift-invariant).
// Grid: (N/256, H, B*2).  Block: 128 threads handling 256 queries.
// ---------------------------------------------------------------------------
__global__ __launch_bounds__(128) void cp_flash2(
    const float* __restrict__ Q1, const float* __restrict__ KV2,
    const float* __restrict__ Beta12, float* __restrict__ O1,
    const float* __restrict__ Q2, const float* __restrict__ KV1,
    const float* __restrict__ Beta21, float* __restrict__ O2)
{
    const int tid = threadIdx.x;
    const int h = blockIdx.y;
    const int z = blockIdx.z;
    const int b = z & 3;
    const int path = z >> 2;

    const float* Q    = path ? Q2     : Q1;
    const float* KV   = path ? KV1    : KV2;
    const float* Beta = path ? Beta21 : Beta12;
    float*       O    = path ? O2     : O1;

    __shared__ float4 ks4[TK][8];
    __shared__ float4 vs4[TK][8];

    const int ia = blockIdx.x * 256 + tid;        // first query
    const int ib = ia + 128;                      // second query

    float qa[32], qb[32], acca[32], accb[32];
    {
        const float4* qpa = (const float4*)(Q + ((size_t)b * NN + ia) * CC + h * DD);
        const float4* qpb = (const float4*)(Q + ((size_t)b * NN + ib) * CC + h * DD);
        #pragma unroll
        for (int dd = 0; dd < 8; dd++) {
            float4 va = qpa[dd], vb = qpb[dd];
            qa[4*dd+0]=va.x; qa[4*dd+1]=va.y; qa[4*dd+2]=va.z; qa[4*dd+3]=va.w;
            qb[4*dd+0]=vb.x; qb[4*dd+1]=vb.y; qb[4*dd+2]=vb.z; qb[4*dd+3]=vb.w;
        }
    }
    #pragma unroll
    for (int d = 0; d < 32; d++) { acca[d] = 0.f; accb[d] = 0.f; }

    const float betav = Beta[h];
    float la = 0.f, lb = 0.f;

    const float* kvb = KV + ((size_t)b * NN) * KVLD + h * DD;

    for (int t = 0; t < NN / TK; t++) {
        // stage 64 keys + 64 values: 512 float4 each, 4 per thread
        #pragma unroll
        for (int it = 0; it < 4; it++) {
            int idx = it * 128 + tid;            // 0..511
            int j = idx >> 3, dd = idx & 7;
            const float4* src = (const float4*)(kvb + (size_t)(t * TK + j) * KVLD) + dd;
            ks4[j][dd] = src[0];
            vs4[j][dd] = src[64];                // +256 floats
        }
        __syncthreads();

        #pragma unroll 1
        for (int j = 0; j < TK; j++) {
            float da0 = 0.f, da1 = 0.f, db0 = 0.f, db1 = 0.f;
            #pragma unroll
            for (int dd = 0; dd < 8; dd++) {
                float4 k4 = ks4[j][dd];
                da0 += qa[4*dd+0] * k4.x; da1 += qa[4*dd+1] * k4.y;
                da0 += qa[4*dd+2] * k4.z; da1 += qa[4*dd+3] * k4.w;
                db0 += qb[4*dd+0] * k4.x; db1 += qb[4*dd+1] * k4.y;
                db0 += qb[4*dd+2] * k4.z; db1 += qb[4*dd+3] * k4.w;
            }
            float pa = __expf((da0 + da1) * SCALE + betav);
            float pb = __expf((db0 + db1) * SCALE + betav);
            la += pa; lb += pb;
            #pragma unroll
            for (int dd = 0; dd < 8; dd++) {
                float4 v4 = vs4[j][dd];
                acca[4*dd+0] += pa * v4.x; acca[4*dd+1] += pa * v4.y;
                acca[4*dd+2] += pa * v4.z; acca[4*dd+3] += pa * v4.w;
                accb[4*dd+0] += pb * v4.x; accb[4*dd+1] += pb * v4.y;
                accb[4*dd+2] += pb * v4.z; accb[4*dd+3] += pb * v4.w;
            }
        }
        __syncthreads();
    }

    const float inva = 1.f / la;
    const float invb = 1.f / lb;
    float4* opa = (float4*)(O + ((size_t)b * NN + ia) * CC + h * DD);
    float4* opb = (float4*)(O + ((size_t)b * NN + ib) * CC + h * DD);
    #pragma unroll
    for (int dd = 0; dd < 8; dd++) {
        float4 oa, ob;
        oa.x = acca[4*dd+0]*inva; oa.y = acca[4*dd+1]*inva;
        oa.z = acca[4*dd+2]*inva; oa.w = acca[4*dd+3]*inva;
        ob.x = accb[4*dd+0]*invb; ob.y = accb[4*dd+1]*invb;
        ob.z = accb[4*dd+2]*invb; ob.w = accb[4*dd+3]*invb;
        opa[dd] = oa;
        opb[dd] = ob;
    }
}

// ---------------------------------------------------------------------------
// LayerNorm over C=256.  One block per row, 256 threads.
// ---------------------------------------------------------------------------
__global__ __launch_bounds__(256) void cp_layernorm(
    const float* __restrict__ Z, const float* __restrict__ g,
    const float* __restrict__ bta, float* __restrict__ Y)
{
    const int row = blockIdx.x;
    const int t = threadIdx.x;
    float v = Z[(size_t)row * CC + t];

    float s = v, q = v * v;
    #pragma unroll
    for (int o = 16; o > 0; o >>= 1) {
        s += __shfl_xor_sync(0xffffffffu, s, o);
        q += __shfl_xor_sync(0xffffffffu, q, o);
    }
    __shared__ float ssum[8], ssq[8];
    if ((t & 31) == 0) { ssum[t >> 5] = s; ssq[t >> 5] = q; }
    __syncthreads();
    __shared__ float smu, sinv;
    if (t == 0) {
        float ts = 0.f, tq = 0.f;
        #pragma unroll
        for (int w = 0; w < 8; w++) { ts += ssum[w]; tq += ssq[w]; }
        float mu = ts * (1.f / CC);
        float var = tq * (1.f / CC) - mu * mu;
        smu = mu;
        sinv = rsqrtf(var + 1e-5f);
    }
    __syncthreads();
    Y[(size_t)row * CC + t] = (v - smu) * sinv * g[t] + bta[t];
}

// ---------------------------------------------------------------------------
// Bilinear upsample x2, half-pixel, [B,N,C] (n=iy*48+ix) -> [B,C,96,96]
// ---------------------------------------------------------------------------
__global__ __launch_bounds__(256) void cp_upsample(
    const float* __restrict__ Y, float* __restrict__ out)
{
    int idx = blockIdx.x * blockDim.x + threadIdx.x;
    if (idx >= OUT_PER_PATH) return;
    int ox = idx % 96;
    int oy = (idx / 96) % 96;
    int c  = (idx / (96 * 96)) % CC;
    int b  = idx / (96 * 96 * CC);

    float sx = ox * 0.5f - 0.25f;
    float sy = oy * 0.5f - 0.25f;
    int x0 = (int)floorf(sx), y0 = (int)floorf(sy);
    float wx = sx - (float)x0, wy = sy - (float)y0;
    int x0c = max(x0, 0), x1c = min(x0 + 1, HDS - 1);
    int y0c = max(y0, 0), y1c = min(y0 + 1, HDS - 1);

    const float* Yb = Y + (size_t)b * NN * CC + c;
    float v00 = Yb[(size_t)(y0c * HDS + x0c) * CC];
    float v01 = Yb[(size_t)(y0c * HDS + x1c) * CC];
    float v10 = Yb[(size_t)(y1c * HDS + x0c) * CC];
    float v11 = Yb[(size_t)(y1c * HDS + x1c) * CC];

    out[idx] = (1.f - wy) * ((1.f - wx) * v00 + wx * v01)
             +        wy  * ((1.f - wx) * v10 + wx * v11);
}

// ---------------------------------------------------------------------------
// Launch
// ---------------------------------------------------------------------------
extern "C" void kernel_launch(void* const* d_in, const int* in_sizes, int n_in,
                              void* d_out, int out_size)
{
    const float* x1     = (const float*)d_in[0];
    const float* x2     = (const float*)d_in[1];
    const float* q1_w   = (const float*)d_in[2];
    const float* kv1_w  = (const float*)d_in[3];
    const float* q2_w   = (const float*)d_in[4];
    const float* kv2_w  = (const float*)d_in[5];
    const float* beta12 = (const float*)d_in[6];
    const float* beta21 = (const float*)d_in[7];
    const float* p1_w   = (const float*)d_in[8];
    const float* p1_b   = (const float*)d_in[9];
    const float* p2_w   = (const float*)d_in[10];
    const float* p2_b   = (const float*)d_in[11];
    const float* g1     = (const float*)d_in[12];
    const float* b1     = (const float*)d_in[13];
    const float* g2     = (const float*)d_in[14];
    const float* b2     = (const float*)d_in[15];
    float* out = (float*)d_out;

    float *q1, *kv1, *q2, *kv2, *o1, *o2, *z1, *z2, *y1, *y2;
    cudaGetSymbolAddress((void**)&q1,  g_q1);
    cudaGetSymbolAddress((void**)&kv1, g_kv1);
    cudaGetSymbolAddress((void**)&q2,  g_q2);
    cudaGetSymbolAddress((void**)&kv2, g_kv2);
    cudaGetSymbolAddress((void**)&o1,  g_o1);
    cudaGetSymbolAddress((void**)&o2,  g_o2);
    cudaGetSymbolAddress((void**)&z1,  g_z1);
    cudaGetSymbolAddress((void**)&z2,  g_z2);
    cudaGetSymbolAddress((void**)&y1,  g_y1);
    cudaGetSymbolAddress((void**)&y2,  g_y2);

    // Projections
    cp_sgemm_nt<<<dim3(CC/128, ROWS/128), 256>>>(x1, q1_w,  nullptr, q1,  ROWS, CC,   CC, 0);
    cp_sgemm_nt<<<dim3(KVLD/128, ROWS/128), 256>>>(x1, kv1_w, nullptr, kv1, ROWS, KVLD, CC, 0);
    cp_sgemm_nt<<<dim3(CC/128, ROWS/128), 256>>>(x2, q2_w,  nullptr, q2,  ROWS, CC,   CC, 0);
    cp_sgemm_nt<<<dim3(KVLD/128, ROWS/128), 256>>>(x2, kv2_w, nullptr, kv2, ROWS, KVLD, CC, 0);

    // Cross attention, both paths
    cp_flash2<<<dim3(NN/256, HH, BB*2), 128>>>(q1, kv2, beta12, o1,
                                               q2, kv1, beta21, o2);

    // Output projection + bias + relu
    cp_sgemm_nt<<<dim3(CC/128, ROWS/128), 256>>>(o1, p1_w, p1_b, z1, ROWS, CC, CC, 1);
    cp_sgemm_nt<<<dim3(CC/128, ROWS/128), 256>>>(o2, p2_w, p2_b, z2, ROWS, CC, CC, 1);

    // LayerNorm
    cp_layernorm<<<ROWS, 256>>>(z1, g1, b1, y1);
    cp_layernorm<<<ROWS, 256>>>(z2, g2, b2, y2);

    // Bilinear upsample x2 -> output (y1 then y2)
    int ublocks = (OUT_PER_PATH + 255) / 256;
    cp_upsample<<<ublocks, 256>>>(y1, out);
    cp_upsample<<<ublocks, 256>>>(y2, out + OUT_PER_PATH);
}

// round 3
// speedup vs baseline: 2.0094x; 1.6570x over previous
#include <cuda_runtime.h>
#include <cuda_bf16.h>
#include <math.h>

// ---------------------------------------------------------------------------
// Problem constants
// ---------------------------------------------------------------------------
#define BB 4
#define NN 2304
#define CC 256
#define HH 8
#define DD 32
#define KVLD 512
#define SCALE 0.17677669529663687f   // 32^-0.5
#define ROWS (BB*NN)                 // 9216
#define HDS 48
#define OUT_PER_PATH (BB*CC*96*96)   // 9437184

// ---------------------------------------------------------------------------
// Scratch
// ---------------------------------------------------------------------------
__device__ __align__(16) float g_q1[ROWS*CC];
__device__ __align__(16) float g_kv1[ROWS*KVLD];
__device__ __align__(16) float g_q2[ROWS*CC];
__device__ __align__(16) float g_kv2[ROWS*KVLD];
__device__ __align__(16) float g_o1[ROWS*CC];
__device__ __align__(16) float g_o2[ROWS*CC];
__device__ __align__(16) float g_z1[ROWS*CC];
__device__ __align__(16) float g_z2[ROWS*CC];
__device__ __align__(16) float g_y1[ROWS*CC];
__device__ __align__(16) float g_y2[ROWS*CC];

// ---------------------------------------------------------------------------
// SGEMM (NT), unchanged from round 2
// ---------------------------------------------------------------------------
__global__ __launch_bounds__(256) void cp_sgemm_nt(
    const float* __restrict__ A, const float* __restrict__ W,
    const float* __restrict__ bias, float* __restrict__ C,
    int M, int Nout, int K, int relu)
{
    __shared__ float As[8][128];
    __shared__ float Bs[8][128];

    const int tid = threadIdx.x;
    const int tx = tid & 15;
    const int ty = tid >> 4;
    const int row0 = blockIdx.y * 128;
    const int col0 = blockIdx.x * 128;

    const int lrow = tid >> 1;
    const int lk4  = (tid & 1) * 4;

    const float* Aptr = A + (size_t)(row0 + lrow) * K + lk4;
    const float* Wptr = W + (size_t)(col0 + lrow) * K + lk4;

    float acc[8][8];
    #pragma unroll
    for (int i = 0; i < 8; i++)
        #pragma unroll
        for (int j = 0; j < 8; j++) acc[i][j] = 0.f;

    for (int k0 = 0; k0 < K; k0 += 8) {
        float4 av = *(const float4*)(Aptr + k0);
        float4 wv = *(const float4*)(Wptr + k0);
        As[lk4+0][lrow] = av.x; As[lk4+1][lrow] = av.y;
        As[lk4+2][lrow] = av.z; As[lk4+3][lrow] = av.w;
        Bs[lk4+0][lrow] = wv.x; Bs[lk4+1][lrow] = wv.y;
        Bs[lk4+2][lrow] = wv.z; Bs[lk4+3][lrow] = wv.w;
        __syncthreads();

        #pragma unroll
        for (int k = 0; k < 8; k++) {
            float a[8], b[8];
            #pragma unroll
            for (int r = 0; r < 8; r++) a[r] = As[k][ty*8 + r];
            #pragma unroll
            for (int r = 0; r < 8; r++) b[r] = Bs[k][tx*8 + r];
            #pragma unroll
            for (int i = 0; i < 8; i++)
                #pragma unroll
                for (int j = 0; j < 8; j++)
                    acc[i][j] += a[i] * b[j];
        }
        __syncthreads();
    }

    #pragma unroll
    for (int i = 0; i < 8; i++) {
        int r = row0 + ty*8 + i;
        #pragma unroll
        for (int j = 0; j < 8; j++) {
            int c = col0 + tx*8 + j;
            float v = acc[i][j];
            if (bias) v += bias[c];
            if (relu) v = fmaxf(v, 0.f);
            C[(size_t)r * Nout + c] = v;
        }
    }
}

// ---------------------------------------------------------------------------
// tf32 m16n8k8 MMA helper
// ---------------------------------------------------------------------------
__device__ __forceinline__ void mma_tf32(
    float& c0, float& c1, float& c2, float& c3,
    unsigned a0, unsigned a1, unsigned a2, unsigned a3,
    unsigned b0, unsigned b1)
{
    asm volatile(
        "mma.sync.aligned.m16n8k8.row.col.f32.tf32.tf32.f32 "
        "{%0,%1,%2,%3}, {%4,%5,%6,%7}, {%8,%9}, {%0,%1,%2,%3};"
        : "+f"(c0), "+f"(c1), "+f"(c2), "+f"(c3)
        : "r"(a0), "r"(a1), "r"(a2), "r"(a3), "r"(b0), "r"(b1));
}

__device__ __forceinline__ unsigned f2tf32(float f)
{
    unsigned r;
    asm("cvt.rna.tf32.f32 %0, %1;" : "=r"(r) : "f"(f));
    return r;
}

// ---------------------------------------------------------------------------
// Flash attention on tensor cores (tf32 mma.sync), exp-immediate softmax.
// Block: 128 threads = 4 warps; 64 queries/block (16/warp); 64-key KV tiles.
// Grid: (N/64, H, B*2).
// ---------------------------------------------------------------------------
#define BC 64
#define KPAD 36
#define PPAD 68

__global__ __launch_bounds__(128) void cp_flash_tc(
    const float* __restrict__ Q1, const float* __restrict__ KV2,
    const float* __restrict__ Beta12, float* __restrict__ O1,
    const float* __restrict__ Q2, const float* __restrict__ KV1,
    const float* __restrict__ Beta21, float* __restrict__ O2)
{
    __shared__ float Ks[BC][KPAD];
    __shared__ float Vs[BC][KPAD];
    __shared__ float Ps[4][16][PPAD];

    const int tid  = threadIdx.x;
    const int w    = tid >> 5;          // warp 0..3
    const int lane = tid & 31;
    const int g    = lane >> 2;         // group 0..7
    const int t4   = lane & 3;          // 0..3

    const int h = blockIdx.y;
    const int z = blockIdx.z;
    const int b = z & 3;
    const int path = z >> 2;

    const float* Q    = path ? Q2     : Q1;
    const float* KV   = path ? KV1    : KV2;
    const float betav = (path ? Beta21 : Beta12)[h];
    float*       O    = path ? O2     : O1;

    const int qrow0 = blockIdx.x * 64 + w * 16;     // warp's first query row

    // ---- load Q fragments (A operand), cvt to tf32 ----
    unsigned Aq[4][4];
    {
        const float* qg0 = Q + ((size_t)b * NN + qrow0 + g    ) * CC + h * DD;
        const float* qg8 = Q + ((size_t)b * NN + qrow0 + g + 8) * CC + h * DD;
        #pragma unroll
        for (int kk = 0; kk < 4; kk++) {
            Aq[kk][0] = f2tf32(qg0[kk*8 + t4]);
            Aq[kk][1] = f2tf32(qg8[kk*8 + t4]);
            Aq[kk][2] = f2tf32(qg0[kk*8 + t4 + 4]);
            Aq[kk][3] = f2tf32(qg8[kk*8 + t4 + 4]);
        }
    }

    float o[4][4];
    #pragma unroll
    for (int n = 0; n < 4; n++)
        #pragma unroll
        for (int e = 0; e < 4; e++) o[n][e] = 0.f;
    float l0 = 0.f, l8 = 0.f;   // row sums for rows g and g+8

    const float* kvb = KV + ((size_t)b * NN) * KVLD + h * DD;

    for (int t = 0; t < NN / BC; t++) {
        if (t) __syncthreads();
        // ---- stage K,V tile (raw fp32 bits; HW truncates to tf32) ----
        #pragma unroll
        for (int it = 0; it < 4; it++) {
            int idx = it * 128 + tid;           // 0..511
            int row = idx >> 3, dd = idx & 7;
            const float4* src = (const float4*)(kvb + (size_t)(t * BC + row) * KVLD) + dd;
            *(float4*)&Ks[row][dd*4] = src[0];
            *(float4*)&Vs[row][dd*4] = src[64]; // +256 floats
        }
        __syncthreads();

        // ---- S = Q @ K^T : 8 n-tiles of 8 keys ----
        float s[8][4];
        #pragma unroll
        for (int j = 0; j < 8; j++) {
            s[j][0] = s[j][1] = s[j][2] = s[j][3] = 0.f;
            #pragma unroll
            for (int kk = 0; kk < 4; kk++) {
                unsigned b0 = __float_as_uint(Ks[j*8 + g][kk*8 + t4]);
                unsigned b1 = __float_as_uint(Ks[j*8 + g][kk*8 + t4 + 4]);
                mma_tf32(s[j][0], s[j][1], s[j][2], s[j][3],
                         Aq[kk][0], Aq[kk][1], Aq[kk][2], Aq[kk][3], b0, b1);
            }
        }

        // ---- softmax (exp-immediate) + write P to shared ----
        float lt0 = 0.f, lt8 = 0.f;
        #pragma unroll
        for (int j = 0; j < 8; j++) {
            float p0 = __expf(s[j][0] * SCALE + betav);
            float p1 = __expf(s[j][1] * SCALE + betav);
            float p2 = __expf(s[j][2] * SCALE + betav);
            float p3 = __expf(s[j][3] * SCALE + betav);
            lt0 += p0 + p1;
            lt8 += p2 + p3;
            *(float2*)&Ps[w][g    ][j*8 + 2*t4] = make_float2(p0, p1);
            *(float2*)&Ps[w][g + 8][j*8 + 2*t4] = make_float2(p2, p3);
        }
        lt0 += __shfl_xor_sync(0xffffffffu, lt0, 1);
        lt0 += __shfl_xor_sync(0xffffffffu, lt0, 2);
        lt8 += __shfl_xor_sync(0xffffffffu, lt8, 1);
        lt8 += __shfl_xor_sync(0xffffffffu, lt8, 2);
        l0 += lt0; l8 += lt8;
        __syncwarp();

        // ---- O += P @ V : k-dim = 64 keys (8 ksteps), n = d (4 tiles) ----
        #pragma unroll
        for (int kk = 0; kk < 8; kk++) {
            unsigned a0 = __float_as_uint(Ps[w][g    ][kk*8 + t4]);
            unsigned a1 = __float_as_uint(Ps[w][g + 8][kk*8 + t4]);
            unsigned a2 = __float_as_uint(Ps[w][g    ][kk*8 + t4 + 4]);
            unsigned a3 = __float_as_uint(Ps[w][g + 8][kk*8 + t4 + 4]);
            #pragma unroll
            for (int n = 0; n < 4; n++) {
                unsigned b0 = __float_as_uint(Vs[kk*8 + t4    ][n*8 + g]);
                unsigned b1 = __float_as_uint(Vs[kk*8 + t4 + 4][n*8 + g]);
                mma_tf32(o[n][0], o[n][1], o[n][2], o[n][3],
                         a0, a1, a2, a3, b0, b1);
            }
        }
        __syncwarp();
    }

    // ---- normalize and store ----
    const float inv0 = 1.f / l0;
    const float inv8 = 1.f / l8;
    float* og0 = O + ((size_t)b * NN + qrow0 + g    ) * CC + h * DD;
    float* og8 = O + ((size_t)b * NN + qrow0 + g + 8) * CC + h * DD;
    #pragma unroll
    for (int n = 0; n < 4; n++) {
        *(float2*)&og0[n*8 + 2*t4] = make_float2(o[n][0]*inv0, o[n][1]*inv0);
        *(float2*)&og8[n*8 + 2*t4] = make_float2(o[n][2]*inv8, o[n][3]*inv8);
    }
}

// ---------------------------------------------------------------------------
// LayerNorm over C=256.
// ---------------------------------------------------------------------------
__global__ __launch_bounds__(256) void cp_layernorm(
    const float* __restrict__ Z, const float* __restrict__ g,
    const float* __restrict__ bta, float* __restrict__ Y)
{
    const int row = blockIdx.x;
    const int t = threadIdx.x;
    float v = Z[(size_t)row * CC + t];

    float s = v, q = v * v;
    #pragma unroll
    for (int o = 16; o > 0; o >>= 1) {
        s += __shfl_xor_sync(0xffffffffu, s, o);
        q += __shfl_xor_sync(0xffffffffu, q, o);
    }
    __shared__ float ssum[8], ssq[8];
    if ((t & 31) == 0) { ssum[t >> 5] = s; ssq[t >> 5] = q; }
    __syncthreads();
    __shared__ float smu, sinv;
    if (t == 0) {
        float ts = 0.f, tq = 0.f;
        #pragma unroll
        for (int w = 0; w < 8; w++) { ts += ssum[w]; tq += ssq[w]; }
        float mu = ts * (1.f / CC);
        float var = tq * (1.f / CC) - mu * mu;
        smu = mu;
        sinv = rsqrtf(var + 1e-5f);
    }
    __syncthreads();
    Y[(size_t)row * CC + t] = (v - smu) * sinv * g[t] + bta[t];
}

// ---------------------------------------------------------------------------
// Bilinear upsample x2
// ---------------------------------------------------------------------------
__global__ __launch_bounds__(256) void cp_upsample(
    const float* __restrict__ Y, float* __restrict__ out)
{
    int idx = blockIdx.x * blockDim.x + threadIdx.x;
    if (idx >= OUT_PER_PATH) return;
    int ox = idx % 96;
    int oy = (idx / 96) % 96;
    int c  = (idx / (96 * 96)) % CC;
    int b  = idx / (96 * 96 * CC);

    float sx = ox * 0.5f - 0.25f;
    float sy = oy * 0.5f - 0.25f;
    int x0 = (int)floorf(sx), y0 = (int)floorf(sy);
    float wx = sx - (float)x0, wy = sy - (float)y0;
    int x0c = max(x0, 0), x1c = min(x0 + 1, HDS - 1);
    int y0c = max(y0, 0), y1c = min(y0 + 1, HDS - 1);

    const float* Yb = Y + (size_t)b * NN * CC + c;
    float v00 = Yb[(size_t)(y0c * HDS + x0c) * CC];
    float v01 = Yb[(size_t)(y0c * HDS + x1c) * CC];
    float v10 = Yb[(size_t)(y1c * HDS + x0c) * CC];
    float v11 = Yb[(size_t)(y1c * HDS + x1c) * CC];

    out[idx] = (1.f - wy) * ((1.f - wx) * v00 + wx * v01)
             +        wy  * ((1.f - wx) * v10 + wx * v11);
}

// ---------------------------------------------------------------------------
// Launch
// ---------------------------------------------------------------------------
extern "C" void kernel_launch(void* const* d_in, const int* in_sizes, int n_in,
                              void* d_out, int out_size)
{
    const float* x1     = (const float*)d_in[0];
    const float* x2     = (const float*)d_in[1];
    const float* q1_w   = (const float*)d_in[2];
    const float* kv1_w  = (const float*)d_in[3];
    const float* q2_w   = (const float*)d_in[4];
    const float* kv2_w  = (const float*)d_in[5];
    const float* beta12 = (const float*)d_in[6];
    const float* beta21 = (const float*)d_in[7];
    const float* p1_w   = (const float*)d_in[8];
    const float* p1_b   = (const float*)d_in[9];
    const float* p2_w   = (const float*)d_in[10];
    const float* p2_b   = (const float*)d_in[11];
    const float* g1     = (const float*)d_in[12];
    const float* b1     = (const float*)d_in[13];
    const float* g2     = (const float*)d_in[14];
    const float* b2     = (const float*)d_in[15];
    float* out = (float*)d_out;

    float *q1, *kv1, *q2, *kv2, *o1, *o2, *z1, *z2, *y1, *y2;
    cudaGetSymbolAddress((void**)&q1,  g_q1);
    cudaGetSymbolAddress((void**)&kv1, g_kv1);
    cudaGetSymbolAddress((void**)&q2,  g_q2);
    cudaGetSymbolAddress((void**)&kv2, g_kv2);
    cudaGetSymbolAddress((void**)&o1,  g_o1);
    cudaGetSymbolAddress((void**)&o2,  g_o2);
    cudaGetSymbolAddress((void**)&z1,  g_z1);
    cudaGetSymbolAddress((void**)&z2,  g_z2);
    cudaGetSymbolAddress((void**)&y1,  g_y1);
    cudaGetSymbolAddress((void**)&y2,  g_y2);

    // Projections
    cp_sgemm_nt<<<dim3(CC/128, ROWS/128), 256>>>(x1, q1_w,  nullptr, q1,  ROWS, CC,   CC, 0);
    cp_sgemm_nt<<<dim3(KVLD/128, ROWS/128), 256>>>(x1, kv1_w, nullptr, kv1, ROWS, KVLD, CC, 0);
    cp_sgemm_nt<<<dim3(CC/128, ROWS/128), 256>>>(x2, q2_w,  nullptr, q2,  ROWS, CC,   CC, 0);
    cp_sgemm_nt<<<dim3(KVLD/128, ROWS/128), 256>>>(x2, kv2_w, nullptr, kv2, ROWS, KVLD, CC, 0);

    // Cross attention on tensor cores
    cp_flash_tc<<<dim3(NN/64, HH, BB*2), 128>>>(q1, kv2, beta12, o1,
                                                q2, kv1, beta21, o2);

    // Output projection + bias + relu
    cp_sgemm_nt<<<dim3(CC/128, ROWS/128), 256>>>(o1, p1_w, p1_b, z1, ROWS, CC, CC, 1);
    cp_sgemm_nt<<<dim3(CC/128, ROWS/128), 256>>>(o2, p2_w, p2_b, z2, ROWS, CC, CC, 1);

    // LayerNorm
    cp_layernorm<<<ROWS, 256>>>(z1, g1, b1, y1);
    cp_layernorm<<<ROWS, 256>>>(z2, g2, b2, y2);

    // Bilinear upsample x2 -> output
    int ublocks = (OUT_PER_PATH + 255) / 256;
    cp_upsample<<<ublocks, 256>>>(y1, out);
    cp_upsample<<<ublocks, 256>>>(y2, out + OUT_PER_PATH);
}

// round 5
// speedup vs baseline: 2.5589x; 1.2735x over previous
#include <cuda_runtime.h>
#include <cuda_bf16.h>
#include <cstdint>
#include <math.h>

// ---------------------------------------------------------------------------
// Problem constants
// ---------------------------------------------------------------------------
#define BB 4
#define NN 2304
#define CC 256
#define HH 8
#define DD 32
#define KVLD 512
#define SCALE 0.17677669529663687f   // 32^-0.5
#define LOG2E 1.4426950408889634f
#define ROWS (BB*NN)                 // 9216
#define HDS 48
#define OUT_PER_PATH (BB*CC*96*96)

// ---------------------------------------------------------------------------
// Scratch
// ---------------------------------------------------------------------------
__device__ __align__(16) float g_q1[ROWS*CC];
__device__ __align__(16) float g_kv1[ROWS*KVLD];
__device__ __align__(16) float g_q2[ROWS*CC];
__device__ __align__(16) float g_kv2[ROWS*KVLD];
__device__ __align__(16) float g_o1[ROWS*CC];
__device__ __align__(16) float g_o2[ROWS*CC];
__device__ __align__(16) float g_z1[ROWS*CC];
__device__ __align__(16) float g_z2[ROWS*CC];
__device__ __align__(16) float g_y1[ROWS*CC];
__device__ __align__(16) float g_y2[ROWS*CC];

// ---------------------------------------------------------------------------
// PTX helpers
// ---------------------------------------------------------------------------
__device__ __forceinline__ void mma_tf32(
    float& c0, float& c1, float& c2, float& c3,
    unsigned a0, unsigned a1, unsigned a2, unsigned a3,
    unsigned b0, unsigned b1)
{
    asm volatile(
        "mma.sync.aligned.m16n8k8.row.col.f32.tf32.tf32.f32 "
        "{%0,%1,%2,%3}, {%4,%5,%6,%7}, {%8,%9}, {%0,%1,%2,%3};"
        : "+f"(c0), "+f"(c1), "+f"(c2), "+f"(c3)
        : "r"(a0), "r"(a1), "r"(a2), "r"(a3), "r"(b0), "r"(b1));
}

__device__ __forceinline__ unsigned f2tf32(float f)
{
    unsigned r;
    asm("cvt.rna.tf32.f32 %0, %1;" : "=r"(r) : "f"(f));
    return r;
}

__device__ __forceinline__ void split_tf32(float x, unsigned& hi, unsigned& lo)
{
    hi = f2tf32(x);
    lo = f2tf32(x - __uint_as_float(hi));
}

__device__ __forceinline__ void cp16(uint32_t dst, const void* src)
{
    asm volatile("cp.async.cg.shared.global [%0], [%1], 16;"
                 :: "r"(dst), "l"(src));
}
#define CP_COMMIT() asm volatile("cp.async.commit_group;")
#define CP_WAIT(n)  asm volatile("cp.async.wait_group %0;" :: "n"(n))

__device__ __forceinline__ uint32_t sptr(const void* p)
{
    return (uint32_t)__cvta_generic_to_shared(p);
}

// ---------------------------------------------------------------------------
// tf32 tensor-core GEMM (NT) with 3xTF32 error compensation (fp32-accurate).
// C[i,j] = act( sum_k A[i,k]*W[j,k] + bias[j] )
// Block 256 thr (8 warps), tile 128x128, kchunk 16, double-buffered cp.async.
// Warp tile 32(m) x 64(n).  Requires M%128==0, Nout%128==0, K%16==0.
// ---------------------------------------------------------------------------
#define GKC 16
#define GKP 20

__global__ __launch_bounds__(256) void cp_gemm_tc(
    const float* __restrict__ A, const float* __restrict__ W,
    const float* __restrict__ bias, float* __restrict__ C,
    int M, int Nout, int K, int relu)
{
    __shared__ __align__(16) float As[2][128][GKP];
    __shared__ __align__(16) float Ws[2][128][GKP];

    const int tid  = threadIdx.x;
    const int w    = tid >> 5;
    const int lane = tid & 31;
    const int g    = lane >> 2;
    const int t4   = lane & 3;
    const int wm   = (w & 3) * 32;
    const int wn   = (w >> 2) * 64;
    const int row0 = blockIdx.y * 128;
    const int col0 = blockIdx.x * 128;

    const int srow = tid >> 1;           // 0..127
    const int sf4  = (tid & 1) * 2;      // float4 index base: 0 or 2

    const float* Abase = A + (size_t)(row0 + srow) * K + sf4 * 4;
    const float* Wbase = W + (size_t)(col0 + srow) * K + sf4 * 4;

    float acc[2][8][4];
    #pragma unroll
    for (int mt = 0; mt < 2; mt++)
        #pragma unroll
        for (int nt = 0; nt < 8; nt++)
            #pragma unroll
            for (int e = 0; e < 4; e++) acc[mt][nt][e] = 0.f;

    const int nchunk = K / GKC;

    // stage chunk t into buffer buf
    auto stage = [&](int t, int buf) {
        #pragma unroll
        for (int j = 0; j < 2; j++) {
            cp16(sptr(&As[buf][srow][(sf4 + j) * 4]), Abase + t * GKC + j * 4);
            cp16(sptr(&Ws[buf][srow][(sf4 + j) * 4]), Wbase + t * GKC + j * 4);
        }
        CP_COMMIT();
    };

    stage(0, 0);

    for (int t = 0; t < nchunk; t++) {
        const int buf = t & 1;
        if (t + 1 < nchunk) { stage(t + 1, buf ^ 1); CP_WAIT(1); }
        else                { CP_WAIT(0); }
        __syncthreads();

        #pragma unroll
        for (int kk = 0; kk < 2; kk++) {
            unsigned ah[2][4], al[2][4];
            #pragma unroll
            for (int mt = 0; mt < 2; mt++) {
                const int r0 = wm + mt * 16 + g;
                split_tf32(As[buf][r0    ][kk*8 + t4    ], ah[mt][0], al[mt][0]);
                split_tf32(As[buf][r0 + 8][kk*8 + t4    ], ah[mt][1], al[mt][1]);
                split_tf32(As[buf][r0    ][kk*8 + t4 + 4], ah[mt][2], al[mt][2]);
                split_tf32(As[buf][r0 + 8][kk*8 + t4 + 4], ah[mt][3], al[mt][3]);
            }
            #pragma unroll
            for (int nt = 0; nt < 8; nt++) {
                unsigned bh0, bl0, bh1, bl1;
                const int rn = wn + nt * 8 + g;
                split_tf32(Ws[buf][rn][kk*8 + t4    ], bh0, bl0);
                split_tf32(Ws[buf][rn][kk*8 + t4 + 4], bh1, bl1);
                #pragma unroll
                for (int mt = 0; mt < 2; mt++) {
                    mma_tf32(acc[mt][nt][0], acc[mt][nt][1], acc[mt][nt][2], acc[mt][nt][3],
                             ah[mt][0], ah[mt][1], ah[mt][2], ah[mt][3], bh0, bh1);
                    mma_tf32(acc[mt][nt][0], acc[mt][nt][1], acc[mt][nt][2], acc[mt][nt][3],
                             al[mt][0], al[mt][1], al[mt][2], al[mt][3], bh0, bh1);
                    mma_tf32(acc[mt][nt][0], acc[mt][nt][1], acc[mt][nt][2], acc[mt][nt][3],
                             ah[mt][0], ah[mt][1], ah[mt][2], ah[mt][3], bl0, bl1);
                }
            }
        }
        __syncthreads();
    }

    // epilogue
    #pragma unroll
    for (int mt = 0; mt < 2; mt++) {
        const int r0 = row0 + wm + mt * 16 + g;
        #pragma unroll
        for (int nt = 0; nt < 8; nt++) {
            const int cg = col0 + wn + nt * 8 + 2 * t4;
            float b0v = 0.f, b1v = 0.f;
            if (bias) { b0v = bias[cg]; b1v = bias[cg + 1]; }
            float v0 = acc[mt][nt][0] + b0v;
            float v1 = acc[mt][nt][1] + b1v;
            float v2 = acc[mt][nt][2] + b0v;
            float v3 = acc[mt][nt][3] + b1v;
            if (relu) {
                v0 = fmaxf(v0, 0.f); v1 = fmaxf(v1, 0.f);
                v2 = fmaxf(v2, 0.f); v3 = fmaxf(v3, 0.f);
            }
            *(float2*)&C[(size_t)r0       * Nout + cg] = make_float2(v0, v1);
            *(float2*)&C[(size_t)(r0 + 8) * Nout + cg] = make_float2(v2, v3);
        }
    }
}

// ---------------------------------------------------------------------------
// Flash attention (tf32 mma.sync), cp.async double-buffered KV staging,
// fused per-8-key slab S -> softmax -> PV with parity-buffered P scratch.
// Block 128 thr (4 warps), 64 queries/block, 64-key tiles.
// ---------------------------------------------------------------------------
#define BC 64
#define KPAD 36
#define PP 12

__global__ __launch_bounds__(128) void cp_flash_tc(
    const float* __restrict__ Q1, const float* __restrict__ KV2,
    const float* __restrict__ Beta12, float* __restrict__ O1,
    const float* __restrict__ Q2, const float* __restrict__ KV1,
    const float* __restrict__ Beta21, float* __restrict__ O2)
{
    __shared__ __align__(16) float Ks[2][BC][KPAD];
    __shared__ __align__(16) float Vs[2][BC][KPAD];
    __shared__ __align__(16) float Ps[4][2][16][PP];

    const int tid  = threadIdx.x;
    const int w    = tid >> 5;
    const int lane = tid & 31;
    const int g    = lane >> 2;
    const int t4   = lane & 3;

    const int h = blockIdx.y;
    const int z = blockIdx.z;
    const int b = z & 3;
    const int path = z >> 2;

    const float* Q    = path ? Q2     : Q1;
    const float* KV   = path ? KV1    : KV2;
    const float betav = (path ? Beta21 : Beta12)[h];
    float*       O    = path ? O2     : O1;

    const float sc2 = SCALE * LOG2E;
    const float b2  = betav * LOG2E;

    const int qrow0 = blockIdx.x * 64 + w * 16;

    // Q fragments
    unsigned Aq[4][4];
    {
        const float* qg0 = Q + ((size_t)b * NN + qrow0 + g    ) * CC + h * DD;
        const float* qg8 = Q + ((size_t)b * NN + qrow0 + g + 8) * CC + h * DD;
        #pragma unroll
        for (int kk = 0; kk < 4; kk++) {
            Aq[kk][0] = f2tf32(qg0[kk*8 + t4]);
            Aq[kk][1] = f2tf32(qg8[kk*8 + t4]);
            Aq[kk][2] = f2tf32(qg0[kk*8 + t4 + 4]);
            Aq[kk][3] = f2tf32(qg8[kk*8 + t4 + 4]);
        }
    }

    float o[4][4];
    #pragma unroll
    for (int n = 0; n < 4; n++)
        #pragma unroll
        for (int e = 0; e < 4; e++) o[n][e] = 0.f;
    float l0 = 0.f, l8 = 0.f;

    const float* kvb = KV + ((size_t)b * NN) * KVLD + h * DD;

    auto stage = [&](int t, int buf) {
        #pragma unroll
        for (int it = 0; it < 4; it++) {
            int idx = it * 128 + tid;          // 0..511
            int row = idx >> 3, dd = idx & 7;
            const float* src = kvb + (size_t)(t * BC + row) * KVLD + dd * 4;
            cp16(sptr(&Ks[buf][row][dd*4]), src);
            cp16(sptr(&Vs[buf][row][dd*4]), src + 256);
        }
        CP_COMMIT();
    };

    stage(0, 0);

    for (int t = 0; t < NN / BC; t++) {
        const int buf = t & 1;
        if (t + 1 < NN / BC) { stage(t + 1, buf ^ 1); CP_WAIT(1); }
        else                 { CP_WAIT(0); }
        __syncthreads();

        #pragma unroll
        for (int j = 0; j < 8; j++) {
            const int pb = j & 1;
            // S_j = Q @ K_j^T  (16 queries x 8 keys)
            float s0 = 0.f, s1 = 0.f, s2 = 0.f, s3 = 0.f;
            #pragma unroll
            for (int kk = 0; kk < 4; kk++) {
                unsigned kb0 = __float_as_uint(Ks[buf][j*8 + g][kk*8 + t4]);
                unsigned kb1 = __float_as_uint(Ks[buf][j*8 + g][kk*8 + t4 + 4]);
                mma_tf32(s0, s1, s2, s3,
                         Aq[kk][0], Aq[kk][1], Aq[kk][2], Aq[kk][3], kb0, kb1);
            }
            // softmax (exp-immediate)
            float p0 = exp2f(s0 * sc2 + b2);
            float p1 = exp2f(s1 * sc2 + b2);
            float p2 = exp2f(s2 * sc2 + b2);
            float p3 = exp2f(s3 * sc2 + b2);
            l0 += p0 + p1;
            l8 += p2 + p3;
            *(float2*)&Ps[w][pb][g    ][2*t4] = make_float2(p0, p1);
            *(float2*)&Ps[w][pb][g + 8][2*t4] = make_float2(p2, p3);
            __syncwarp();
            // O += P_j @ V_j  (k-step of 8 keys)
            unsigned a0 = __float_as_uint(Ps[w][pb][g    ][t4    ]);
            unsigned a1 = __float_as_uint(Ps[w][pb][g + 8][t4    ]);
            unsigned a2 = __float_as_uint(Ps[w][pb][g    ][t4 + 4]);
            unsigned a3 = __float_as_uint(Ps[w][pb][g + 8][t4 + 4]);
            #pragma unroll
            for (int n = 0; n < 4; n++) {
                unsigned vb0 = __float_as_uint(Vs[buf][j*8 + t4    ][n*8 + g]);
                unsigned vb1 = __float_as_uint(Vs[buf][j*8 + t4 + 4][n*8 + g]);
                mma_tf32(o[n][0], o[n][1], o[n][2], o[n][3],
                         a0, a1, a2, a3, vb0, vb1);
            }
        }
        __syncthreads();
    }

    // reduce row sums across the quad and store
    l0 += __shfl_xor_sync(0xffffffffu, l0, 1);
    l0 += __shfl_xor_sync(0xffffffffu, l0, 2);
    l8 += __shfl_xor_sync(0xffffffffu, l8, 1);
    l8 += __shfl_xor_sync(0xffffffffu, l8, 2);
    const float inv0 = 1.f / l0;
    const float inv8 = 1.f / l8;
    float* og0 = O + ((size_t)b * NN + qrow0 + g    ) * CC + h * DD;
    float* og8 = O + ((size_t)b * NN + qrow0 + g + 8) * CC + h * DD;
    #pragma unroll
    for (int n = 0; n < 4; n++) {
        *(float2*)&og0[n*8 + 2*t4] = make_float2(o[n][0]*inv0, o[n][1]*inv0);
        *(float2*)&og8[n*8 + 2*t4] = make_float2(o[n][2]*inv8, o[n][3]*inv8);
    }
}

// ---------------------------------------------------------------------------
// LayerNorm over C=256
// ---------------------------------------------------------------------------
__global__ __launch_bounds__(256) void cp_layernorm(
    const float* __restrict__ Z, const float* __restrict__ g,
    const float* __restrict__ bta, float* __restrict__ Y)
{
    const int row = blockIdx.x;
    const int t = threadIdx.x;
    float v = Z[(size_t)row * CC + t];

    float s = v, q = v * v;
    #pragma unroll
    for (int o = 16; o > 0; o >>= 1) {
        s += __shfl_xor_sync(0xffffffffu, s, o);
        q += __shfl_xor_sync(0xffffffffu, q, o);
    }
    __shared__ float ssum[8], ssq[8];
    if ((t & 31) == 0) { ssum[t >> 5] = s; ssq[t >> 5] = q; }
    __syncthreads();
    __shared__ float smu, sinv;
    if (t == 0) {
        float ts = 0.f, tq = 0.f;
        #pragma unroll
        for (int w = 0; w < 8; w++) { ts += ssum[w]; tq += ssq[w]; }
        float mu = ts * (1.f / CC);
        float var = tq * (1.f / CC) - mu * mu;
        smu = mu;
        sinv = rsqrtf(var + 1e-5f);
    }
    __syncthreads();
    Y[(size_t)row * CC + t] = (v - smu) * sinv * g[t] + bta[t];
}

// ---------------------------------------------------------------------------
// Bilinear upsample x2
// ---------------------------------------------------------------------------
__global__ __launch_bounds__(256) void cp_upsample(
    const float* __restrict__ Y, float* __restrict__ out)
{
    int idx = blockIdx.x * blockDim.x + threadIdx.x;
    if (idx >= OUT_PER_PATH) return;
    int ox = idx % 96;
    int oy = (idx / 96) % 96;
    int c  = (idx / (96 * 96)) % CC;
    int b  = idx / (96 * 96 * CC);

    float sx = ox * 0.5f - 0.25f;
    float sy = oy * 0.5f - 0.25f;
    int x0 = (int)floorf(sx), y0 = (int)floorf(sy);
    float wx = sx - (float)x0, wy = sy - (float)y0;
    int x0c = max(x0, 0), x1c = min(x0 + 1, HDS - 1);
    int y0c = max(y0, 0), y1c = min(y0 + 1, HDS - 1);

    const float* Yb = Y + (size_t)b * NN * CC + c;
    float v00 = Yb[(size_t)(y0c * HDS + x0c) * CC];
    float v01 = Yb[(size_t)(y0c * HDS + x1c) * CC];
    float v10 = Yb[(size_t)(y1c * HDS + x0c) * CC];
    float v11 = Yb[(size_t)(y1c * HDS + x1c) * CC];

    out[idx] = (1.f - wy) * ((1.f - wx) * v00 + wx * v01)
             +        wy  * ((1.f - wx) * v10 + wx * v11);
}

// ---------------------------------------------------------------------------
// Launch
// ---------------------------------------------------------------------------
extern "C" void kernel_launch(void* const* d_in, const int* in_sizes, int n_in,
                              void* d_out, int out_size)
{
    const float* x1     = (const float*)d_in[0];
    const float* x2     = (const float*)d_in[1];
    const float* q1_w   = (const float*)d_in[2];
    const float* kv1_w  = (const float*)d_in[3];
    const float* q2_w   = (const float*)d_in[4];
    const float* kv2_w  = (const float*)d_in[5];
    const float* beta12 = (const float*)d_in[6];
    const float* beta21 = (const float*)d_in[7];
    const float* p1_w   = (const float*)d_in[8];
    const float* p1_b   = (const float*)d_in[9];
    const float* p2_w   = (const float*)d_in[10];
    const float* p2_b   = (const float*)d_in[11];
    const float* g1     = (const float*)d_in[12];
    const float* b1     = (const float*)d_in[13];
    const float* g2     = (const float*)d_in[14];
    const float* b2     = (const float*)d_in[15];
    float* out = (float*)d_out;

    float *q1, *kv1, *q2, *kv2, *o1, *o2, *z1, *z2, *y1, *y2;
    cudaGetSymbolAddress((void**)&q1,  g_q1);
    cudaGetSymbolAddress((void**)&kv1, g_kv1);
    cudaGetSymbolAddress((void**)&q2,  g_q2);
    cudaGetSymbolAddress((void**)&kv2, g_kv2);
    cudaGetSymbolAddress((void**)&o1,  g_o1);
    cudaGetSymbolAddress((void**)&o2,  g_o2);
    cudaGetSymbolAddress((void**)&z1,  g_z1);
    cudaGetSymbolAddress((void**)&z2,  g_z2);
    cudaGetSymbolAddress((void**)&y1,  g_y1);
    cudaGetSymbolAddress((void**)&y2,  g_y2);

    // Projections (3xTF32 tensor-core GEMM)
    cp_gemm_tc<<<dim3(CC/128,   ROWS/128), 256>>>(x1, q1_w,  nullptr, q1,  ROWS, CC,   CC, 0);
    cp_gemm_tc<<<dim3(KVLD/128, ROWS/128), 256>>>(x1, kv1_w, nullptr, kv1, ROWS, KVLD, CC, 0);
    cp_gemm_tc<<<dim3(CC/128,   ROWS/128), 256>>>(x2, q2_w,  nullptr, q2,  ROWS, CC,   CC, 0);
    cp_gemm_tc<<<dim3(KVLD/128, ROWS/128), 256>>>(x2, kv2_w, nullptr, kv2, ROWS, KVLD, CC, 0);

    // Cross attention on tensor cores
    cp_flash_tc<<<dim3(NN/64, HH, BB*2), 128>>>(q1, kv2, beta12, o1,
                                                q2, kv1, beta21, o2);

    // Output projection + bias + relu
    cp_gemm_tc<<<dim3(CC/128, ROWS/128), 256>>>(o1, p1_w, p1_b, z1, ROWS, CC, CC, 1);
    cp_gemm_tc<<<dim3(CC/128, ROWS/128), 256>>>(o2, p2_w, p2_b, z2, ROWS, CC, CC, 1);

    // LayerNorm
    cp_layernorm<<<ROWS, 256>>>(z1, g1, b1, y1);
    cp_layernorm<<<ROWS, 256>>>(z2, g2, b2, y2);

    // Bilinear upsample x2 -> output
    int ublocks = (OUT_PER_PATH + 255) / 256;
    cp_upsample<<<ublocks, 256>>>(y1, out);
    cp_upsample<<<ublocks, 256>>>(y2, out + OUT_PER_PATH);
}

// round 6
// speedup vs baseline: 2.8740x; 1.1231x over previous
#include <cuda_runtime.h>
#include <cuda_bf16.h>
#include <cstdint>
#include <math.h>

// ---------------------------------------------------------------------------
// Problem constants
// ---------------------------------------------------------------------------
#define BB 4
#define NN 2304
#define CC 256
#define HH 8
#define DD 32
#define KVLD 512
#define SCALE 0.17677669529663687f   // 32^-0.5
#define LOG2E 1.4426950408889634f
#define ROWS (BB*NN)                 // 9216
#define HDS 48
#define OUT_PER_PATH (BB*CC*96*96)

// ---------------------------------------------------------------------------
// Scratch
// ---------------------------------------------------------------------------
__device__ __align__(16) float g_q1[ROWS*CC];
__device__ __align__(16) float g_kv1[ROWS*KVLD];
__device__ __align__(16) float g_q2[ROWS*CC];
__device__ __align__(16) float g_kv2[ROWS*KVLD];
__device__ __align__(16) float g_o1[ROWS*CC];
__device__ __align__(16) float g_o2[ROWS*CC];
__device__ __align__(16) float g_z1[ROWS*CC];
__device__ __align__(16) float g_z2[ROWS*CC];
__device__ __align__(16) float g_y1[ROWS*CC];
__device__ __align__(16) float g_y2[ROWS*CC];

// ---------------------------------------------------------------------------
// PTX helpers
// ---------------------------------------------------------------------------
__device__ __forceinline__ void mma_tf32(
    float& c0, float& c1, float& c2, float& c3,
    unsigned a0, unsigned a1, unsigned a2, unsigned a3,
    unsigned b0, unsigned b1)
{
    asm volatile(
        "mma.sync.aligned.m16n8k8.row.col.f32.tf32.tf32.f32 "
        "{%0,%1,%2,%3}, {%4,%5,%6,%7}, {%8,%9}, {%0,%1,%2,%3};"
        : "+f"(c0), "+f"(c1), "+f"(c2), "+f"(c3)
        : "r"(a0), "r"(a1), "r"(a2), "r"(a3), "r"(b0), "r"(b1));
}

__device__ __forceinline__ unsigned f2tf32(float f)
{
    unsigned r;
    asm("cvt.rna.tf32.f32 %0, %1;" : "=r"(r) : "f"(f));
    return r;
}

__device__ __forceinline__ void cp16(uint32_t dst, const void* src)
{
    asm volatile("cp.async.cg.shared.global [%0], [%1], 16;"
                 :: "r"(dst), "l"(src));
}
#define CP_COMMIT() asm volatile("cp.async.commit_group;")
#define CP_WAIT(n)  asm volatile("cp.async.wait_group %0;" :: "n"(n))

__device__ __forceinline__ uint32_t sptr(const void* p)
{
    return (uint32_t)__cvta_generic_to_shared(p);
}

// ---------------------------------------------------------------------------
// tf32 tensor-core GEMM (NT), 3xTF32 error compensation, splits hoisted:
// each k-chunk is split ONCE into shared float2(hi,lo); inner loop is pure
// LDS.64 + HMMA. Register double-buffered staging (LDG prefetch), dynamic smem.
// Block 256 thr (8 warps), tile 128x128, kchunk 16, warp tile 32x64.
// ---------------------------------------------------------------------------
#define GKC 16
#define GP2 20      // float2 pitch per row
#define GEMM_SMEM (2 * 2 * 128 * GP2 * (int)sizeof(float2))   // 81920 B

__global__ __launch_bounds__(256) void cp_gemm_tc(
    const float* __restrict__ A, const float* __restrict__ W,
    const float* __restrict__ bias, float* __restrict__ C,
    int M, int Nout, int K, int relu)
{
    extern __shared__ __align__(16) float2 smem2[];
    float2* As2 = smem2;                        // [2][128][GP2]
    float2* Ws2 = smem2 + 2 * 128 * GP2;        // [2][128][GP2]

    const int tid  = threadIdx.x;
    const int w    = tid >> 5;
    const int lane = tid & 31;
    const int g    = lane >> 2;
    const int t4   = lane & 3;
    const int wm   = (w & 3) * 32;
    const int wn   = (w >> 2) * 64;
    const int row0 = blockIdx.y * 128;
    const int col0 = blockIdx.x * 128;

    const int srow = tid >> 1;           // 0..127
    const int sf8  = (tid & 1) * 8;      // k offset: 0 or 8

    const float* Abase = A + (size_t)(row0 + srow) * K + sf8;
    const float* Wbase = W + (size_t)(col0 + srow) * K + sf8;

    float acc[2][8][4];
    #pragma unroll
    for (int mt = 0; mt < 2; mt++)
        #pragma unroll
        for (int nt = 0; nt < 8; nt++)
            #pragma unroll
            for (int e = 0; e < 4; e++) acc[mt][nt][e] = 0.f;

    const int nchunk = K / GKC;

    float4 ra0, ra1, rw0, rw1;
    auto loadregs = [&](int t) {
        ra0 = *(const float4*)(Abase + t * GKC);
        ra1 = *(const float4*)(Abase + t * GKC + 4);
        rw0 = *(const float4*)(Wbase + t * GKC);
        rw1 = *(const float4*)(Wbase + t * GKC + 4);
    };
    auto storeregs = [&](int buf) {
        float xa[8] = {ra0.x, ra0.y, ra0.z, ra0.w, ra1.x, ra1.y, ra1.z, ra1.w};
        float xw[8] = {rw0.x, rw0.y, rw0.z, rw0.w, rw1.x, rw1.y, rw1.z, rw1.w};
        float2* da = &As2[(buf * 128 + srow) * GP2 + sf8];
        float2* dw = &Ws2[(buf * 128 + srow) * GP2 + sf8];
        #pragma unroll
        for (int i = 0; i < 8; i += 2) {
            unsigned h0 = f2tf32(xa[i]);
            unsigned l0 = f2tf32(xa[i]   - __uint_as_float(h0));
            unsigned h1 = f2tf32(xa[i+1]);
            unsigned l1 = f2tf32(xa[i+1] - __uint_as_float(h1));
            *(float4*)&da[i] = make_float4(__uint_as_float(h0), __uint_as_float(l0),
                                           __uint_as_float(h1), __uint_as_float(l1));
            h0 = f2tf32(xw[i]);
            l0 = f2tf32(xw[i]   - __uint_as_float(h0));
            h1 = f2tf32(xw[i+1]);
            l1 = f2tf32(xw[i+1] - __uint_as_float(h1));
            *(float4*)&dw[i] = make_float4(__uint_as_float(h0), __uint_as_float(l0),
                                           __uint_as_float(h1), __uint_as_float(l1));
        }
    };

    loadregs(0);

    for (int t = 0; t < nchunk; t++) {
        const int buf = t & 1;
        storeregs(buf);
        __syncthreads();
        if (t + 1 < nchunk) loadregs(t + 1);

        #pragma unroll
        for (int kk = 0; kk < 2; kk++) {
            float2 av[2][4];
            #pragma unroll
            for (int mt = 0; mt < 2; mt++) {
                const int r0 = wm + mt * 16 + g;
                av[mt][0] = As2[(buf * 128 + r0    ) * GP2 + kk*8 + t4    ];
                av[mt][1] = As2[(buf * 128 + r0 + 8) * GP2 + kk*8 + t4    ];
                av[mt][2] = As2[(buf * 128 + r0    ) * GP2 + kk*8 + t4 + 4];
                av[mt][3] = As2[(buf * 128 + r0 + 8) * GP2 + kk*8 + t4 + 4];
            }
            #pragma unroll
            for (int nt = 0; nt < 8; nt++) {
                const int rn = wn + nt * 8 + g;
                float2 wv0 = Ws2[(buf * 128 + rn) * GP2 + kk*8 + t4    ];
                float2 wv1 = Ws2[(buf * 128 + rn) * GP2 + kk*8 + t4 + 4];
                unsigned bh0 = __float_as_uint(wv0.x), bl0 = __float_as_uint(wv0.y);
                unsigned bh1 = __float_as_uint(wv1.x), bl1 = __float_as_uint(wv1.y);
                #pragma unroll
                for (int mt = 0; mt < 2; mt++) {
                    unsigned ah0 = __float_as_uint(av[mt][0].x), al0 = __float_as_uint(av[mt][0].y);
                    unsigned ah1 = __float_as_uint(av[mt][1].x), al1 = __float_as_uint(av[mt][1].y);
                    unsigned ah2 = __float_as_uint(av[mt][2].x), al2 = __float_as_uint(av[mt][2].y);
                    unsigned ah3 = __float_as_uint(av[mt][3].x), al3 = __float_as_uint(av[mt][3].y);
                    mma_tf32(acc[mt][nt][0], acc[mt][nt][1], acc[mt][nt][2], acc[mt][nt][3],
                             ah0, ah1, ah2, ah3, bh0, bh1);
                    mma_tf32(acc[mt][nt][0], acc[mt][nt][1], acc[mt][nt][2], acc[mt][nt][3],
                             al0, al1, al2, al3, bh0, bh1);
                    mma_tf32(acc[mt][nt][0], acc[mt][nt][1], acc[mt][nt][2], acc[mt][nt][3],
                             ah0, ah1, ah2, ah3, bl0, bl1);
                }
            }
        }
    }

    // epilogue
    #pragma unroll
    for (int mt = 0; mt < 2; mt++) {
        const int r0 = row0 + wm + mt * 16 + g;
        #pragma unroll
        for (int nt = 0; nt < 8; nt++) {
            const int cg = col0 + wn + nt * 8 + 2 * t4;
            float b0v = 0.f, b1v = 0.f;
            if (bias) { b0v = bias[cg]; b1v = bias[cg + 1]; }
            float v0 = acc[mt][nt][0] + b0v;
            float v1 = acc[mt][nt][1] + b1v;
            float v2 = acc[mt][nt][2] + b0v;
            float v3 = acc[mt][nt][3] + b1v;
            if (relu) {
                v0 = fmaxf(v0, 0.f); v1 = fmaxf(v1, 0.f);
                v2 = fmaxf(v2, 0.f); v3 = fmaxf(v3, 0.f);
            }
            *(float2*)&C[(size_t)r0       * Nout + cg] = make_float2(v0, v1);
            *(float2*)&C[(size_t)(r0 + 8) * Nout + cg] = make_float2(v2, v3);
        }
    }
}

// ---------------------------------------------------------------------------
// Flash attention (tf32 mma.sync): 2 query-tiles per warp (32 q/warp,
// 128 q/block), cp.async double-buffered KV, fused per-8-key slab.
// KPAD=40 -> conflict-free K (8g+t4) and V (8t4+g) LDS patterns.
// ---------------------------------------------------------------------------
#define BC 64
#define KPAD 40
#define PP 8

__global__ __launch_bounds__(128) void cp_flash_tc(
    const float* __restrict__ Q1, const float* __restrict__ KV2,
    const float* __restrict__ Beta12, float* __restrict__ O1,
    const float* __restrict__ Q2, const float* __restrict__ KV1,
    const float* __restrict__ Beta21, float* __restrict__ O2)
{
    __shared__ __align__(16) float Ks[2][BC][KPAD];
    __shared__ __align__(16) float Vs[2][BC][KPAD];
    __shared__ __align__(16) float Ps[4][2][2][16][PP];

    const int tid  = threadIdx.x;
    const int w    = tid >> 5;
    const int lane = tid & 31;
    const int g    = lane >> 2;
    const int t4   = lane & 3;

    const int h = blockIdx.y;
    const int z = blockIdx.z;
    const int b = z & 3;
    const int path = z >> 2;

    const float* Q    = path ? Q2     : Q1;
    const float* KV   = path ? KV1    : KV2;
    const float betav = (path ? Beta21 : Beta12)[h];
    float*       O    = path ? O2     : O1;

    const float sc2 = SCALE * LOG2E;
    const float bb2 = betav * LOG2E;

    const int qrow0 = blockIdx.x * 128 + w * 32;

    // Q fragments for both tiles
    unsigned Aq[2][4][4];
    #pragma unroll
    for (int tt = 0; tt < 2; tt++) {
        const float* qg0 = Q + ((size_t)b * NN + qrow0 + tt*16 + g    ) * CC + h * DD;
        const float* qg8 = Q + ((size_t)b * NN + qrow0 + tt*16 + g + 8) * CC + h * DD;
        #pragma unroll
        for (int kk = 0; kk < 4; kk++) {
            Aq[tt][kk][0] = f2tf32(qg0[kk*8 + t4]);
            Aq[tt][kk][1] = f2tf32(qg8[kk*8 + t4]);
            Aq[tt][kk][2] = f2tf32(qg0[kk*8 + t4 + 4]);
            Aq[tt][kk][3] = f2tf32(qg8[kk*8 + t4 + 4]);
        }
    }

    float o[2][4][4];
    #pragma unroll
    for (int tt = 0; tt < 2; tt++)
        #pragma unroll
        for (int n = 0; n < 4; n++)
            #pragma unroll
            for (int e = 0; e < 4; e++) o[tt][n][e] = 0.f;
    float l0[2] = {0.f, 0.f}, l8[2] = {0.f, 0.f};

    const float* kvb = KV + ((size_t)b * NN) * KVLD + h * DD;

    auto stage = [&](int t, int buf) {
        #pragma unroll
        for (int it = 0; it < 4; it++) {
            int idx = it * 128 + tid;          // 0..511
            int row = idx >> 3, dd = idx & 7;
            const float* src = kvb + (size_t)(t * BC + row) * KVLD + dd * 4;
            cp16(sptr(&Ks[buf][row][dd*4]), src);
            cp16(sptr(&Vs[buf][row][dd*4]), src + 256);
        }
        CP_COMMIT();
    };

    stage(0, 0);

    for (int t = 0; t < NN / BC; t++) {
        const int buf = t & 1;
        if (t + 1 < NN / BC) { stage(t + 1, buf ^ 1); CP_WAIT(1); }
        else                 { CP_WAIT(0); }
        __syncthreads();

        #pragma unroll
        for (int j = 0; j < 8; j++) {
            const int pb = j & 1;
            // S = Q @ K_j^T for both q-tiles
            float s[2][4];
            #pragma unroll
            for (int tt = 0; tt < 2; tt++)
                s[tt][0] = s[tt][1] = s[tt][2] = s[tt][3] = 0.f;
            #pragma unroll
            for (int kk = 0; kk < 4; kk++) {
                unsigned kb0 = __float_as_uint(Ks[buf][j*8 + g][kk*8 + t4]);
                unsigned kb1 = __float_as_uint(Ks[buf][j*8 + g][kk*8 + t4 + 4]);
                mma_tf32(s[0][0], s[0][1], s[0][2], s[0][3],
                         Aq[0][kk][0], Aq[0][kk][1], Aq[0][kk][2], Aq[0][kk][3], kb0, kb1);
                mma_tf32(s[1][0], s[1][1], s[1][2], s[1][3],
                         Aq[1][kk][0], Aq[1][kk][1], Aq[1][kk][2], Aq[1][kk][3], kb0, kb1);
            }
            // softmax (exp-immediate) + P to shared
            #pragma unroll
            for (int tt = 0; tt < 2; tt++) {
                float p0 = exp2f(s[tt][0] * sc2 + bb2);
                float p1 = exp2f(s[tt][1] * sc2 + bb2);
                float p2 = exp2f(s[tt][2] * sc2 + bb2);
                float p3 = exp2f(s[tt][3] * sc2 + bb2);
                l0[tt] += p0 + p1;
                l8[tt] += p2 + p3;
                *(float2*)&Ps[w][pb][tt][g    ][2*t4] = make_float2(p0, p1);
                *(float2*)&Ps[w][pb][tt][g + 8][2*t4] = make_float2(p2, p3);
            }
            __syncwarp();
            // P fragments
            unsigned a[2][4];
            #pragma unroll
            for (int tt = 0; tt < 2; tt++) {
                a[tt][0] = __float_as_uint(Ps[w][pb][tt][g    ][t4    ]);
                a[tt][1] = __float_as_uint(Ps[w][pb][tt][g + 8][t4    ]);
                a[tt][2] = __float_as_uint(Ps[w][pb][tt][g    ][t4 + 4]);
                a[tt][3] = __float_as_uint(Ps[w][pb][tt][g + 8][t4 + 4]);
            }
            // O += P_j @ V_j
            #pragma unroll
            for (int n = 0; n < 4; n++) {
                unsigned vb0 = __float_as_uint(Vs[buf][j*8 + t4    ][n*8 + g]);
                unsigned vb1 = __float_as_uint(Vs[buf][j*8 + t4 + 4][n*8 + g]);
                mma_tf32(o[0][n][0], o[0][n][1], o[0][n][2], o[0][n][3],
                         a[0][0], a[0][1], a[0][2], a[0][3], vb0, vb1);
                mma_tf32(o[1][n][0], o[1][n][1], o[1][n][2], o[1][n][3],
                         a[1][0], a[1][1], a[1][2], a[1][3], vb0, vb1);
            }
        }
        __syncthreads();
    }

    // reduce row sums and store both tiles
    #pragma unroll
    for (int tt = 0; tt < 2; tt++) {
        l0[tt] += __shfl_xor_sync(0xffffffffu, l0[tt], 1);
        l0[tt] += __shfl_xor_sync(0xffffffffu, l0[tt], 2);
        l8[tt] += __shfl_xor_sync(0xffffffffu, l8[tt], 1);
        l8[tt] += __shfl_xor_sync(0xffffffffu, l8[tt], 2);
        const float inv0 = 1.f / l0[tt];
        const float inv8 = 1.f / l8[tt];
        float* og0 = O + ((size_t)b * NN + qrow0 + tt*16 + g    ) * CC + h * DD;
        float* og8 = O + ((size_t)b * NN + qrow0 + tt*16 + g + 8) * CC + h * DD;
        #pragma unroll
        for (int n = 0; n < 4; n++) {
            *(float2*)&og0[n*8 + 2*t4] = make_float2(o[tt][n][0]*inv0, o[tt][n][1]*inv0);
            *(float2*)&og8[n*8 + 2*t4] = make_float2(o[tt][n][2]*inv8, o[tt][n][3]*inv8);
        }
    }
}

// ---------------------------------------------------------------------------
// LayerNorm over C=256
// ---------------------------------------------------------------------------
__global__ __launch_bounds__(256) void cp_layernorm(
    const float* __restrict__ Z, const float* __restrict__ g,
    const float* __restrict__ bta, float* __restrict__ Y)
{
    const int row = blockIdx.x;
    const int t = threadIdx.x;
    float v = Z[(size_t)row * CC + t];

    float s = v, q = v * v;
    #pragma unroll
    for (int o = 16; o > 0; o >>= 1) {
        s += __shfl_xor_sync(0xffffffffu, s, o);
        q += __shfl_xor_sync(0xffffffffu, q, o);
    }
    __shared__ float ssum[8], ssq[8];
    if ((t & 31) == 0) { ssum[t >> 5] = s; ssq[t >> 5] = q; }
    __syncthreads();
    __shared__ float smu, sinv;
    if (t == 0) {
        float ts = 0.f, tq = 0.f;
        #pragma unroll
        for (int w = 0; w < 8; w++) { ts += ssum[w]; tq += ssq[w]; }
        float mu = ts * (1.f / CC);
        float var = tq * (1.f / CC) - mu * mu;
        smu = mu;
        sinv = rsqrtf(var + 1e-5f);
    }
    __syncthreads();
    Y[(size_t)row * CC + t] = (v - smu) * sinv * g[t] + bta[t];
}

// ---------------------------------------------------------------------------
// Bilinear upsample x2
// ---------------------------------------------------------------------------
__global__ __launch_bounds__(256) void cp_upsample(
    const float* __restrict__ Y, float* __restrict__ out)
{
    int idx = blockIdx.x * blockDim.x + threadIdx.x;
    if (idx >= OUT_PER_PATH) return;
    int ox = idx % 96;
    int oy = (idx / 96) % 96;
    int c  = (idx / (96 * 96)) % CC;
    int b  = idx / (96 * 96 * CC);

    float sx = ox * 0.5f - 0.25f;
    float sy = oy * 0.5f - 0.25f;
    int x0 = (int)floorf(sx), y0 = (int)floorf(sy);
    float wx = sx - (float)x0, wy = sy - (float)y0;
    int x0c = max(x0, 0), x1c = min(x0 + 1, HDS - 1);
    int y0c = max(y0, 0), y1c = min(y0 + 1, HDS - 1);

    const float* Yb = Y + (size_t)b * NN * CC + c;
    float v00 = Yb[(size_t)(y0c * HDS + x0c) * CC];
    float v01 = Yb[(size_t)(y0c * HDS + x1c) * CC];
    float v10 = Yb[(size_t)(y1c * HDS + x0c) * CC];
    float v11 = Yb[(size_t)(y1c * HDS + x1c) * CC];

    out[idx] = (1.f - wy) * ((1.f - wx) * v00 + wx * v01)
             +        wy  * ((1.f - wx) * v10 + wx * v11);
}

// ---------------------------------------------------------------------------
// Launch
// ---------------------------------------------------------------------------
extern "C" void kernel_launch(void* const* d_in, const int* in_sizes, int n_in,
                              void* d_out, int out_size)
{
    const float* x1     = (const float*)d_in[0];
    const float* x2     = (const float*)d_in[1];
    const float* q1_w   = (const float*)d_in[2];
    const float* kv1_w  = (const float*)d_in[3];
    const float* q2_w   = (const float*)d_in[4];
    const float* kv2_w  = (const float*)d_in[5];
    const float* beta12 = (const float*)d_in[6];
    const float* beta21 = (const float*)d_in[7];
    const float* p1_w   = (const float*)d_in[8];
    const float* p1_b   = (const float*)d_in[9];
    const float* p2_w   = (const float*)d_in[10];
    const float* p2_b   = (const float*)d_in[11];
    const float* g1     = (const float*)d_in[12];
    const float* b1     = (const float*)d_in[13];
    const float* g2     = (const float*)d_in[14];
    const float* b2     = (const float*)d_in[15];
    float* out = (float*)d_out;

    float *q1, *kv1, *q2, *kv2, *o1, *o2, *z1, *z2, *y1, *y2;
    cudaGetSymbolAddress((void**)&q1,  g_q1);
    cudaGetSymbolAddress((void**)&kv1, g_kv1);
    cudaGetSymbolAddress((void**)&q2,  g_q2);
    cudaGetSymbolAddress((void**)&kv2, g_kv2);
    cudaGetSymbolAddress((void**)&o1,  g_o1);
    cudaGetSymbolAddress((void**)&o2,  g_o2);
    cudaGetSymbolAddress((void**)&z1,  g_z1);
    cudaGetSymbolAddress((void**)&z2,  g_z2);
    cudaGetSymbolAddress((void**)&y1,  g_y1);
    cudaGetSymbolAddress((void**)&y2,  g_y2);

    static bool attr_set = false;
    if (!attr_set) {
        cudaFuncSetAttribute(cp_gemm_tc,
                             cudaFuncAttributeMaxDynamicSharedMemorySize,
                             GEMM_SMEM);
        attr_set = true;
    }

    // Projections (3xTF32 tensor-core GEMM, hoisted splits)
    cp_gemm_tc<<<dim3(CC/128,   ROWS/128), 256, GEMM_SMEM>>>(x1, q1_w,  nullptr, q1,  ROWS, CC,   CC, 0);
    cp_gemm_tc<<<dim3(KVLD/128, ROWS/128), 256, GEMM_SMEM>>>(x1, kv1_w, nullptr, kv1, ROWS, KVLD, CC, 0);
    cp_gemm_tc<<<dim3(CC/128,   ROWS/128), 256, GEMM_SMEM>>>(x2, q2_w,  nullptr, q2,  ROWS, CC,   CC, 0);
    cp_gemm_tc<<<dim3(KVLD/128, ROWS/128), 256, GEMM_SMEM>>>(x2, kv2_w, nullptr, kv2, ROWS, KVLD, CC, 0);

    // Cross attention on tensor cores (128 queries/block)
    cp_flash_tc<<<dim3(NN/128, HH, BB*2), 128>>>(q1, kv2, beta12, o1,
                                                 q2, kv1, beta21, o2);

    // Output projection + bias + relu
    cp_gemm_tc<<<dim3(CC/128, ROWS/128), 256, GEMM_SMEM>>>(o1, p1_w, p1_b, z1, ROWS, CC, CC, 1);
    cp_gemm_tc<<<dim3(CC/128, ROWS/128), 256, GEMM_SMEM>>>(o2, p2_w, p2_b, z2, ROWS, CC, CC, 1);

    // LayerNorm
    cp_layernorm<<<ROWS, 256>>>(z1, g1, b1, y1);
    cp_layernorm<<<ROWS, 256>>>(z2, g2, b2, y2);

    // Bilinear upsample x2 -> output
    int ublocks = (OUT_PER_PATH + 255) / 256;
    cp_upsample<<<ublocks, 256>>>(y1, out);
    cp_upsample<<<ublocks, 256>>>(y2, out + OUT_PER_PATH);
}

// round 7
// speedup vs baseline: 3.0670x; 1.0671x over previous
#include <cuda_runtime.h>
#include <cuda_bf16.h>
#include <cstdint>
#include <math.h>

// ---------------------------------------------------------------------------
// Problem constants
// ---------------------------------------------------------------------------
#define BB 4
#define NN 2304
#define CC 256
#define HH 8
#define DD 32
#define KVLD 512
#define SCALE 0.17677669529663687f   // 32^-0.5
#define LOG2E 1.4426950408889634f
#define ROWS (BB*NN)                 // 9216
#define HDS 48
#define OUT_PER_PATH (BB*CC*96*96)

// ---------------------------------------------------------------------------
// Scratch
// ---------------------------------------------------------------------------
__device__ __align__(16) float g_q1[ROWS*CC];
__device__ __align__(16) float g_kv1[ROWS*KVLD];
__device__ __align__(16) float g_q2[ROWS*CC];
__device__ __align__(16) float g_kv2[ROWS*KVLD];
__device__ __align__(16) float g_o1[ROWS*CC];
__device__ __align__(16) float g_o2[ROWS*CC];
__device__ __align__(16) float g_z1[ROWS*CC];
__device__ __align__(16) float g_z2[ROWS*CC];
__device__ __align__(16) float g_y1[ROWS*CC];
__device__ __align__(16) float g_y2[ROWS*CC];

// ---------------------------------------------------------------------------
// PTX helpers
// ---------------------------------------------------------------------------
__device__ __forceinline__ void mma_tf32(
    float& c0, float& c1, float& c2, float& c3,
    unsigned a0, unsigned a1, unsigned a2, unsigned a3,
    unsigned b0, unsigned b1)
{
    asm volatile(
        "mma.sync.aligned.m16n8k8.row.col.f32.tf32.tf32.f32 "
        "{%0,%1,%2,%3}, {%4,%5,%6,%7}, {%8,%9}, {%0,%1,%2,%3};"
        : "+f"(c0), "+f"(c1), "+f"(c2), "+f"(c3)
        : "r"(a0), "r"(a1), "r"(a2), "r"(a3), "r"(b0), "r"(b1));
}

__device__ __forceinline__ unsigned f2tf32(float f)
{
    unsigned r;
    asm("cvt.rna.tf32.f32 %0, %1;" : "=r"(r) : "f"(f));
    return r;
}

__device__ __forceinline__ void split_tf32(float x, unsigned& hi, unsigned& lo)
{
    hi = f2tf32(x);
    lo = f2tf32(x - __uint_as_float(hi));
}

__device__ __forceinline__ void cp16(uint32_t dst, const void* src)
{
    asm volatile("cp.async.cg.shared.global [%0], [%1], 16;"
                 :: "r"(dst), "l"(src));
}
#define CP_COMMIT() asm volatile("cp.async.commit_group;")
#define CP_WAIT(n)  asm volatile("cp.async.wait_group %0;" :: "n"(n))

__device__ __forceinline__ uint32_t sptr(const void* p)
{
    return (uint32_t)__cvta_generic_to_shared(p);
}

// ---------------------------------------------------------------------------
// tf32 tensor-core GEMM (NT) with 3xTF32 error compensation (fp32-accurate).
// [Round-5 version: in-register splits, static smem, cp.async double-buffer.]
// Block 256 thr (8 warps), tile 128x128, kchunk 16, warp tile 32x64.
// ---------------------------------------------------------------------------
#define GKC 16
#define GKP 20

__global__ __launch_bounds__(256) void cp_gemm_tc(
    const float* __restrict__ A, const float* __restrict__ W,
    const float* __restrict__ bias, float* __restrict__ C,
    int M, int Nout, int K, int relu)
{
    __shared__ __align__(16) float As[2][128][GKP];
    __shared__ __align__(16) float Ws[2][128][GKP];

    const int tid  = threadIdx.x;
    const int w    = tid >> 5;
    const int lane = tid & 31;
    const int g    = lane >> 2;
    const int t4   = lane & 3;
    const int wm   = (w & 3) * 32;
    const int wn   = (w >> 2) * 64;
    const int row0 = blockIdx.y * 128;
    const int col0 = blockIdx.x * 128;

    const int srow = tid >> 1;           // 0..127
    const int sf4  = (tid & 1) * 2;      // float4 index base: 0 or 2

    const float* Abase = A + (size_t)(row0 + srow) * K + sf4 * 4;
    const float* Wbase = W + (size_t)(col0 + srow) * K + sf4 * 4;

    float acc[2][8][4];
    #pragma unroll
    for (int mt = 0; mt < 2; mt++)
        #pragma unroll
        for (int nt = 0; nt < 8; nt++)
            #pragma unroll
            for (int e = 0; e < 4; e++) acc[mt][nt][e] = 0.f;

    const int nchunk = K / GKC;

    auto stage = [&](int t, int buf) {
        #pragma unroll
        for (int j = 0; j < 2; j++) {
            cp16(sptr(&As[buf][srow][(sf4 + j) * 4]), Abase + t * GKC + j * 4);
            cp16(sptr(&Ws[buf][srow][(sf4 + j) * 4]), Wbase + t * GKC + j * 4);
        }
        CP_COMMIT();
    };

    stage(0, 0);

    for (int t = 0; t < nchunk; t++) {
        const int buf = t & 1;
        if (t + 1 < nchunk) { stage(t + 1, buf ^ 1); CP_WAIT(1); }
        else                { CP_WAIT(0); }
        __syncthreads();

        #pragma unroll
        for (int kk = 0; kk < 2; kk++) {
            unsigned ah[2][4], al[2][4];
            #pragma unroll
            for (int mt = 0; mt < 2; mt++) {
                const int r0 = wm + mt * 16 + g;
                split_tf32(As[buf][r0    ][kk*8 + t4    ], ah[mt][0], al[mt][0]);
                split_tf32(As[buf][r0 + 8][kk*8 + t4    ], ah[mt][1], al[mt][1]);
                split_tf32(As[buf][r0    ][kk*8 + t4 + 4], ah[mt][2], al[mt][2]);
                split_tf32(As[buf][r0 + 8][kk*8 + t4 + 4], ah[mt][3], al[mt][3]);
            }
            #pragma unroll
            for (int nt = 0; nt < 8; nt++) {
                unsigned bh0, bl0, bh1, bl1;
                const int rn = wn + nt * 8 + g;
                split_tf32(Ws[buf][rn][kk*8 + t4    ], bh0, bl0);
                split_tf32(Ws[buf][rn][kk*8 + t4 + 4], bh1, bl1);
                #pragma unroll
                for (int mt = 0; mt < 2; mt++) {
                    mma_tf32(acc[mt][nt][0], acc[mt][nt][1], acc[mt][nt][2], acc[mt][nt][3],
                             ah[mt][0], ah[mt][1], ah[mt][2], ah[mt][3], bh0, bh1);
                    mma_tf32(acc[mt][nt][0], acc[mt][nt][1], acc[mt][nt][2], acc[mt][nt][3],
                             al[mt][0], al[mt][1], al[mt][2], al[mt][3], bh0, bh1);
                    mma_tf32(acc[mt][nt][0], acc[mt][nt][1], acc[mt][nt][2], acc[mt][nt][3],
                             ah[mt][0], ah[mt][1], ah[mt][2], ah[mt][3], bl0, bl1);
                }
            }
        }
        __syncthreads();
    }

    // epilogue
    #pragma unroll
    for (int mt = 0; mt < 2; mt++) {
        const int r0 = row0 + wm + mt * 16 + g;
        #pragma unroll
        for (int nt = 0; nt < 8; nt++) {
            const int cg = col0 + wn + nt * 8 + 2 * t4;
            float b0v = 0.f, b1v = 0.f;
            if (bias) { b0v = bias[cg]; b1v = bias[cg + 1]; }
            float v0 = acc[mt][nt][0] + b0v;
            float v1 = acc[mt][nt][1] + b1v;
            float v2 = acc[mt][nt][2] + b0v;
            float v3 = acc[mt][nt][3] + b1v;
            if (relu) {
                v0 = fmaxf(v0, 0.f); v1 = fmaxf(v1, 0.f);
                v2 = fmaxf(v2, 0.f); v3 = fmaxf(v3, 0.f);
            }
            *(float2*)&C[(size_t)r0       * Nout + cg] = make_float2(v0, v1);
            *(float2*)&C[(size_t)(r0 + 8) * Nout + cg] = make_float2(v2, v3);
        }
    }
}

// ---------------------------------------------------------------------------
// Flash attention (tf32 mma.sync): 4 query-tiles per warp (64 q/warp,
// 256 q/block), cp.async double-buffered KV, fused per-8-key slab.
// KPAD=40 -> conflict-free K (8g+t4) and V (8t4+g) LDS patterns.
// ---------------------------------------------------------------------------
#define BC 64
#define KPAD 40
#define PP 8
#define TT 4

__global__ __launch_bounds__(128) void cp_flash_tc(
    const float* __restrict__ Q1, const float* __restrict__ KV2,
    const float* __restrict__ Beta12, float* __restrict__ O1,
    const float* __restrict__ Q2, const float* __restrict__ KV1,
    const float* __restrict__ Beta21, float* __restrict__ O2)
{
    __shared__ __align__(16) float Ks[2][BC][KPAD];
    __shared__ __align__(16) float Vs[2][BC][KPAD];
    __shared__ __align__(16) float Ps[4][2][TT][16][PP];

    const int tid  = threadIdx.x;
    const int w    = tid >> 5;
    const int lane = tid & 31;
    const int g    = lane >> 2;
    const int t4   = lane & 3;

    const int h = blockIdx.y;
    const int z = blockIdx.z;
    const int b = z & 3;
    const int path = z >> 2;

    const float* Q    = path ? Q2     : Q1;
    const float* KV   = path ? KV1    : KV2;
    const float betav = (path ? Beta21 : Beta12)[h];
    float*       O    = path ? O2     : O1;

    const float sc2 = SCALE * LOG2E;
    const float bb2 = betav * LOG2E;

    const int qrow0 = blockIdx.x * (TT * 64) + w * (TT * 16);

    // Q fragments for TT tiles
    unsigned Aq[TT][4][4];
    #pragma unroll
    for (int tt = 0; tt < TT; tt++) {
        const float* qg0 = Q + ((size_t)b * NN + qrow0 + tt*16 + g    ) * CC + h * DD;
        const float* qg8 = Q + ((size_t)b * NN + qrow0 + tt*16 + g + 8) * CC + h * DD;
        #pragma unroll
        for (int kk = 0; kk < 4; kk++) {
            Aq[tt][kk][0] = f2tf32(qg0[kk*8 + t4]);
            Aq[tt][kk][1] = f2tf32(qg8[kk*8 + t4]);
            Aq[tt][kk][2] = f2tf32(qg0[kk*8 + t4 + 4]);
            Aq[tt][kk][3] = f2tf32(qg8[kk*8 + t4 + 4]);
        }
    }

    float o[TT][4][4];
    #pragma unroll
    for (int tt = 0; tt < TT; tt++)
        #pragma unroll
        for (int n = 0; n < 4; n++)
            #pragma unroll
            for (int e = 0; e < 4; e++) o[tt][n][e] = 0.f;
    float l0[TT], l8[TT];
    #pragma unroll
    for (int tt = 0; tt < TT; tt++) { l0[tt] = 0.f; l8[tt] = 0.f; }

    const float* kvb = KV + ((size_t)b * NN) * KVLD + h * DD;

    auto stage = [&](int t, int buf) {
        #pragma unroll
        for (int it = 0; it < 4; it++) {
            int idx = it * 128 + tid;          // 0..511
            int row = idx >> 3, dd = idx & 7;
            const float* src = kvb + (size_t)(t * BC + row) * KVLD + dd * 4;
            cp16(sptr(&Ks[buf][row][dd*4]), src);
            cp16(sptr(&Vs[buf][row][dd*4]), src + 256);
        }
        CP_COMMIT();
    };

    stage(0, 0);

    for (int t = 0; t < NN / BC; t++) {
        const int buf = t & 1;
        if (t + 1 < NN / BC) { stage(t + 1, buf ^ 1); CP_WAIT(1); }
        else                 { CP_WAIT(0); }
        __syncthreads();

        #pragma unroll
        for (int j = 0; j < 8; j++) {
            const int pb = j & 1;
            // S = Q @ K_j^T for all q-tiles
            float s[TT][4];
            #pragma unroll
            for (int tt = 0; tt < TT; tt++)
                s[tt][0] = s[tt][1] = s[tt][2] = s[tt][3] = 0.f;
            #pragma unroll
            for (int kk = 0; kk < 4; kk++) {
                unsigned kb0 = __float_as_uint(Ks[buf][j*8 + g][kk*8 + t4]);
                unsigned kb1 = __float_as_uint(Ks[buf][j*8 + g][kk*8 + t4 + 4]);
                #pragma unroll
                for (int tt = 0; tt < TT; tt++)
                    mma_tf32(s[tt][0], s[tt][1], s[tt][2], s[tt][3],
                             Aq[tt][kk][0], Aq[tt][kk][1], Aq[tt][kk][2], Aq[tt][kk][3],
                             kb0, kb1);
            }
            // softmax (exp-immediate) + P to shared
            #pragma unroll
            for (int tt = 0; tt < TT; tt++) {
                float p0 = exp2f(s[tt][0] * sc2 + bb2);
                float p1 = exp2f(s[tt][1] * sc2 + bb2);
                float p2 = exp2f(s[tt][2] * sc2 + bb2);
                float p3 = exp2f(s[tt][3] * sc2 + bb2);
                l0[tt] += p0 + p1;
                l8[tt] += p2 + p3;
                *(float2*)&Ps[w][pb][tt][g    ][2*t4] = make_float2(p0, p1);
                *(float2*)&Ps[w][pb][tt][g + 8][2*t4] = make_float2(p2, p3);
            }
            __syncwarp();
            // P fragments
            unsigned a[TT][4];
            #pragma unroll
            for (int tt = 0; tt < TT; tt++) {
                a[tt][0] = __float_as_uint(Ps[w][pb][tt][g    ][t4    ]);
                a[tt][1] = __float_as_uint(Ps[w][pb][tt][g + 8][t4    ]);
                a[tt][2] = __float_as_uint(Ps[w][pb][tt][g    ][t4 + 4]);
                a[tt][3] = __float_as_uint(Ps[w][pb][tt][g + 8][t4 + 4]);
            }
            // O += P_j @ V_j
            #pragma unroll
            for (int n = 0; n < 4; n++) {
                unsigned vb0 = __float_as_uint(Vs[buf][j*8 + t4    ][n*8 + g]);
                unsigned vb1 = __float_as_uint(Vs[buf][j*8 + t4 + 4][n*8 + g]);
                #pragma unroll
                for (int tt = 0; tt < TT; tt++)
                    mma_tf32(o[tt][n][0], o[tt][n][1], o[tt][n][2], o[tt][n][3],
                             a[tt][0], a[tt][1], a[tt][2], a[tt][3], vb0, vb1);
            }
        }
        __syncthreads();
    }

    // reduce row sums and store all tiles
    #pragma unroll
    for (int tt = 0; tt < TT; tt++) {
        l0[tt] += __shfl_xor_sync(0xffffffffu, l0[tt], 1);
        l0[tt] += __shfl_xor_sync(0xffffffffu, l0[tt], 2);
        l8[tt] += __shfl_xor_sync(0xffffffffu, l8[tt], 1);
        l8[tt] += __shfl_xor_sync(0xffffffffu, l8[tt], 2);
        const float inv0 = 1.f / l0[tt];
        const float inv8 = 1.f / l8[tt];
        float* og0 = O + ((size_t)b * NN + qrow0 + tt*16 + g    ) * CC + h * DD;
        float* og8 = O + ((size_t)b * NN + qrow0 + tt*16 + g + 8) * CC + h * DD;
        #pragma unroll
        for (int n = 0; n < 4; n++) {
            *(float2*)&og0[n*8 + 2*t4] = make_float2(o[tt][n][0]*inv0, o[tt][n][1]*inv0);
            *(float2*)&og8[n*8 + 2*t4] = make_float2(o[tt][n][2]*inv8, o[tt][n][3]*inv8);
        }
    }
}

// ---------------------------------------------------------------------------
// LayerNorm over C=256
// ---------------------------------------------------------------------------
__global__ __launch_bounds__(256) void cp_layernorm(
    const float* __restrict__ Z, const float* __restrict__ g,
    const float* __restrict__ bta, float* __restrict__ Y)
{
    const int row = blockIdx.x;
    const int t = threadIdx.x;
    float v = Z[(size_t)row * CC + t];

    float s = v, q = v * v;
    #pragma unroll
    for (int o = 16; o > 0; o >>= 1) {
        s += __shfl_xor_sync(0xffffffffu, s, o);
        q += __shfl_xor_sync(0xffffffffu, q, o);
    }
    __shared__ float ssum[8], ssq[8];
    if ((t & 31) == 0) { ssum[t >> 5] = s; ssq[t >> 5] = q; }
    __syncthreads();
    __shared__ float smu, sinv;
    if (t == 0) {
        float ts = 0.f, tq = 0.f;
        #pragma unroll
        for (int w = 0; w < 8; w++) { ts += ssum[w]; tq += ssq[w]; }
        float mu = ts * (1.f / CC);
        float var = tq * (1.f / CC) - mu * mu;
        smu = mu;
        sinv = rsqrtf(var + 1e-5f);
    }
    __syncthreads();
    Y[(size_t)row * CC + t] = (v - smu) * sinv * g[t] + bta[t];
}

// ---------------------------------------------------------------------------
// Bilinear upsample x2
// ---------------------------------------------------------------------------
__global__ __launch_bounds__(256) void cp_upsample(
    const float* __restrict__ Y, float* __restrict__ out)
{
    int idx = blockIdx.x * blockDim.x + threadIdx.x;
    if (idx >= OUT_PER_PATH) return;
    int ox = idx % 96;
    int oy = (idx / 96) % 96;
    int c  = (idx / (96 * 96)) % CC;
    int b  = idx / (96 * 96 * CC);

    float sx = ox * 0.5f - 0.25f;
    float sy = oy * 0.5f - 0.25f;
    int x0 = (int)floorf(sx), y0 = (int)floorf(sy);
    float wx = sx - (float)x0, wy = sy - (float)y0;
    int x0c = max(x0, 0), x1c = min(x0 + 1, HDS - 1);
    int y0c = max(y0, 0), y1c = min(y0 + 1, HDS - 1);

    const float* Yb = Y + (size_t)b * NN * CC + c;
    float v00 = Yb[(size_t)(y0c * HDS + x0c) * CC];
    float v01 = Yb[(size_t)(y0c * HDS + x1c) * CC];
    float v10 = Yb[(size_t)(y1c * HDS + x0c) * CC];
    float v11 = Yb[(size_t)(y1c * HDS + x1c) * CC];

    out[idx] = (1.f - wy) * ((1.f - wx) * v00 + wx * v01)
             +        wy  * ((1.f - wx) * v10 + wx * v11);
}

// ---------------------------------------------------------------------------
// Launch
// ---------------------------------------------------------------------------
extern "C" void kernel_launch(void* const* d_in, const int* in_sizes, int n_in,
                              void* d_out, int out_size)
{
    const float* x1     = (const float*)d_in[0];
    const float* x2     = (const float*)d_in[1];
    const float* q1_w   = (const float*)d_in[2];
    const float* kv1_w  = (const float*)d_in[3];
    const float* q2_w   = (const float*)d_in[4];
    const float* kv2_w  = (const float*)d_in[5];
    const float* beta12 = (const float*)d_in[6];
    const float* beta21 = (const float*)d_in[7];
    const float* p1_w   = (const float*)d_in[8];
    const float* p1_b   = (const float*)d_in[9];
    const float* p2_w   = (const float*)d_in[10];
    const float* p2_b   = (const float*)d_in[11];
    const float* g1     = (const float*)d_in[12];
    const float* b1     = (const float*)d_in[13];
    const float* g2     = (const float*)d_in[14];
    const float* b2     = (const float*)d_in[15];
    float* out = (float*)d_out;

    float *q1, *kv1, *q2, *kv2, *o1, *o2, *z1, *z2, *y1, *y2;
    cudaGetSymbolAddress((void**)&q1,  g_q1);
    cudaGetSymbolAddress((void**)&kv1, g_kv1);
    cudaGetSymbolAddress((void**)&q2,  g_q2);
    cudaGetSymbolAddress((void**)&kv2, g_kv2);
    cudaGetSymbolAddress((void**)&o1,  g_o1);
    cudaGetSymbolAddress((void**)&o2,  g_o2);
    cudaGetSymbolAddress((void**)&z1,  g_z1);
    cudaGetSymbolAddress((void**)&z2,  g_z2);
    cudaGetSymbolAddress((void**)&y1,  g_y1);
    cudaGetSymbolAddress((void**)&y2,  g_y2);

    // Projections (3xTF32 tensor-core GEMM)
    cp_gemm_tc<<<dim3(CC/128,   ROWS/128), 256>>>(x1, q1_w,  nullptr, q1,  ROWS, CC,   CC, 0);
    cp_gemm_tc<<<dim3(KVLD/128, ROWS/128), 256>>>(x1, kv1_w, nullptr, kv1, ROWS, KVLD, CC, 0);
    cp_gemm_tc<<<dim3(CC/128,   ROWS/128), 256>>>(x2, q2_w,  nullptr, q2,  ROWS, CC,   CC, 0);
    cp_gemm_tc<<<dim3(KVLD/128, ROWS/128), 256>>>(x2, kv2_w, nullptr, kv2, ROWS, KVLD, CC, 0);

    // Cross attention on tensor cores (256 queries/block)
    cp_flash_tc<<<dim3(NN/256, HH, BB*2), 128>>>(q1, kv2, beta12, o1,
                                                 q2, kv1, beta21, o2);

    // Output projection + bias + relu
    cp_gemm_tc<<<dim3(CC/128, ROWS/128), 256>>>(o1, p1_w, p1_b, z1, ROWS, CC, CC, 1);
    cp_gemm_tc<<<dim3(CC/128, ROWS/128), 256>>>(o2, p2_w, p2_b, z2, ROWS, CC, CC, 1);

    // LayerNorm
    cp_layernorm<<<ROWS, 256>>>(z1, g1, b1, y1);
    cp_layernorm<<<ROWS, 256>>>(z2, g2, b2, y2);

    // Bilinear upsample x2 -> output
    int ublocks = (OUT_PER_PATH + 255) / 256;
    cp_upsample<<<ublocks, 256>>>(y1, out);
    cp_upsample<<<ublocks, 256>>>(y2, out + OUT_PER_PATH);
}

// round 8
// speedup vs baseline: 3.4242x; 1.1165x over previous
#include <cuda_runtime.h>
#include <cuda_bf16.h>
#include <cstdint>
#include <math.h>

// ---------------------------------------------------------------------------
// Problem constants
// ---------------------------------------------------------------------------
#define BB 4
#define NN 2304
#define CC 256
#define HH 8
#define DD 32
#define KVLD 512
#define SCALE 0.17677669529663687f   // 32^-0.5
#define LOG2E 1.4426950408889634f
#define ROWS (BB*NN)                 // 9216
#define HDS 48
#define OUT_PER_PATH (BB*CC*96*96)

// ---------------------------------------------------------------------------
// Scratch
// ---------------------------------------------------------------------------
__device__ __align__(16) float g_q1[ROWS*CC];
__device__ __align__(16) float g_kv1[ROWS*KVLD];
__device__ __align__(16) float g_q2[ROWS*CC];
__device__ __align__(16) float g_kv2[ROWS*KVLD];
__device__ __align__(16) float g_o1[ROWS*CC];
__device__ __align__(16) float g_o2[ROWS*CC];
__device__ __align__(16) float g_z1[ROWS*CC];
__device__ __align__(16) float g_z2[ROWS*CC];
__device__ __align__(16) float g_y1[ROWS*CC];
__device__ __align__(16) float g_y2[ROWS*CC];

// ---------------------------------------------------------------------------
// PTX helpers
// ---------------------------------------------------------------------------
__device__ __forceinline__ void mma_tf32(
    float& c0, float& c1, float& c2, float& c3,
    unsigned a0, unsigned a1, unsigned a2, unsigned a3,
    unsigned b0, unsigned b1)
{
    asm volatile(
        "mma.sync.aligned.m16n8k8.row.col.f32.tf32.tf32.f32 "
        "{%0,%1,%2,%3}, {%4,%5,%6,%7}, {%8,%9}, {%0,%1,%2,%3};"
        : "+f"(c0), "+f"(c1), "+f"(c2), "+f"(c3)
        : "r"(a0), "r"(a1), "r"(a2), "r"(a3), "r"(b0), "r"(b1));
}

__device__ __forceinline__ unsigned f2tf32(float f)
{
    unsigned r;
    asm("cvt.rna.tf32.f32 %0, %1;" : "=r"(r) : "f"(f));
    return r;
}

__device__ __forceinline__ void split_tf32(float x, unsigned& hi, unsigned& lo)
{
    hi = f2tf32(x);
    lo = f2tf32(x - __uint_as_float(hi));
}

__device__ __forceinline__ void cp16(uint32_t dst, const void* src)
{
    asm volatile("cp.async.cg.shared.global [%0], [%1], 16;"
                 :: "r"(dst), "l"(src));
}
#define CP_COMMIT() asm volatile("cp.async.commit_group;")
#define CP_WAIT(n)  asm volatile("cp.async.wait_group %0;" :: "n"(n))

__device__ __forceinline__ uint32_t sptr(const void* p)
{
    return (uint32_t)__cvta_generic_to_shared(p);
}

// ---------------------------------------------------------------------------
// tf32 tensor-core GEMM (NT) with 3xTF32 error compensation (fp32-accurate).
// [Proven round-5/7 version: in-register splits, static smem, cp.async.]
// ---------------------------------------------------------------------------
#define GKC 16
#define GKP 20

__global__ __launch_bounds__(256) void cp_gemm_tc(
    const float* __restrict__ A, const float* __restrict__ W,
    const float* __restrict__ bias, float* __restrict__ C,
    int M, int Nout, int K, int relu)
{
    __shared__ __align__(16) float As[2][128][GKP];
    __shared__ __align__(16) float Ws[2][128][GKP];

    const int tid  = threadIdx.x;
    const int w    = tid >> 5;
    const int lane = tid & 31;
    const int g    = lane >> 2;
    const int t4   = lane & 3;
    const int wm   = (w & 3) * 32;
    const int wn   = (w >> 2) * 64;
    const int row0 = blockIdx.y * 128;
    const int col0 = blockIdx.x * 128;

    const int srow = tid >> 1;
    const int sf4  = (tid & 1) * 2;

    const float* Abase = A + (size_t)(row0 + srow) * K + sf4 * 4;
    const float* Wbase = W + (size_t)(col0 + srow) * K + sf4 * 4;

    float acc[2][8][4];
    #pragma unroll
    for (int mt = 0; mt < 2; mt++)
        #pragma unroll
        for (int nt = 0; nt < 8; nt++)
            #pragma unroll
            for (int e = 0; e < 4; e++) acc[mt][nt][e] = 0.f;

    const int nchunk = K / GKC;

    auto stage = [&](int t, int buf) {
        #pragma unroll
        for (int j = 0; j < 2; j++) {
            cp16(sptr(&As[buf][srow][(sf4 + j) * 4]), Abase + t * GKC + j * 4);
            cp16(sptr(&Ws[buf][srow][(sf4 + j) * 4]), Wbase + t * GKC + j * 4);
        }
        CP_COMMIT();
    };

    stage(0, 0);

    for (int t = 0; t < nchunk; t++) {
        const int buf = t & 1;
        if (t + 1 < nchunk) { stage(t + 1, buf ^ 1); CP_WAIT(1); }
        else                { CP_WAIT(0); }
        __syncthreads();

        #pragma unroll
        for (int kk = 0; kk < 2; kk++) {
            unsigned ah[2][4], al[2][4];
            #pragma unroll
            for (int mt = 0; mt < 2; mt++) {
                const int r0 = wm + mt * 16 + g;
                split_tf32(As[buf][r0    ][kk*8 + t4    ], ah[mt][0], al[mt][0]);
                split_tf32(As[buf][r0 + 8][kk*8 + t4    ], ah[mt][1], al[mt][1]);
                split_tf32(As[buf][r0    ][kk*8 + t4 + 4], ah[mt][2], al[mt][2]);
                split_tf32(As[buf][r0 + 8][kk*8 + t4 + 4], ah[mt][3], al[mt][3]);
            }
            #pragma unroll
            for (int nt = 0; nt < 8; nt++) {
                unsigned bh0, bl0, bh1, bl1;
                const int rn = wn + nt * 8 + g;
                split_tf32(Ws[buf][rn][kk*8 + t4    ], bh0, bl0);
                split_tf32(Ws[buf][rn][kk*8 + t4 + 4], bh1, bl1);
                #pragma unroll
                for (int mt = 0; mt < 2; mt++) {
                    mma_tf32(acc[mt][nt][0], acc[mt][nt][1], acc[mt][nt][2], acc[mt][nt][3],
                             ah[mt][0], ah[mt][1], ah[mt][2], ah[mt][3], bh0, bh1);
                    mma_tf32(acc[mt][nt][0], acc[mt][nt][1], acc[mt][nt][2], acc[mt][nt][3],
                             al[mt][0], al[mt][1], al[mt][2], al[mt][3], bh0, bh1);
                    mma_tf32(acc[mt][nt][0], acc[mt][nt][1], acc[mt][nt][2], acc[mt][nt][3],
                             ah[mt][0], ah[mt][1], ah[mt][2], ah[mt][3], bl0, bl1);
                }
            }
        }
        __syncthreads();
    }

    #pragma unroll
    for (int mt = 0; mt < 2; mt++) {
        const int r0 = row0 + wm + mt * 16 + g;
        #pragma unroll
        for (int nt = 0; nt < 8; nt++) {
            const int cg = col0 + wn + nt * 8 + 2 * t4;
            float b0v = 0.f, b1v = 0.f;
            if (bias) { b0v = bias[cg]; b1v = bias[cg + 1]; }
            float v0 = acc[mt][nt][0] + b0v;
            float v1 = acc[mt][nt][1] + b1v;
            float v2 = acc[mt][nt][2] + b0v;
            float v3 = acc[mt][nt][3] + b1v;
            if (relu) {
                v0 = fmaxf(v0, 0.f); v1 = fmaxf(v1, 0.f);
                v2 = fmaxf(v2, 0.f); v3 = fmaxf(v3, 0.f);
            }
            *(float2*)&C[(size_t)r0       * Nout + cg] = make_float2(v0, v1);
            *(float2*)&C[(size_t)(r0 + 8) * Nout + cg] = make_float2(v2, v3);
        }
    }
}

// ---------------------------------------------------------------------------
// Flash attention (tf32 mma.sync), 4 q-tiles/warp, cp.async double-buffer.
// KEY-PERMUTED V staging: V global key (8j+c) is stored at shared slot
// (8j + pi(c)), pi(c) = (c&1) ? (c>>1)+4 : (c>>1).  With this permutation the
// exp outputs (p0,p2,p1,p3) ARE the PV A-operand fragment -> no P shared
// round-trip, no syncwarp inside the slab loop.
// ---------------------------------------------------------------------------
#define BC 64
#define KPAD 40
#define TT 4

__global__ __launch_bounds__(128) void cp_flash_tc(
    const float* __restrict__ Q1, const float* __restrict__ KV2,
    const float* __restrict__ Beta12, float* __restrict__ O1,
    const float* __restrict__ Q2, const float* __restrict__ KV1,
    const float* __restrict__ Beta21, float* __restrict__ O2)
{
    __shared__ __align__(16) float Ks[2][BC][KPAD];
    __shared__ __align__(16) float Vs[2][BC][KPAD];

    const int tid  = threadIdx.x;
    const int lane = tid & 31;
    const int w    = tid >> 5;
    const int g    = lane >> 2;
    const int t4   = lane & 3;

    const int h = blockIdx.y;
    const int z = blockIdx.z;
    const int b = z & 3;
    const int path = z >> 2;

    const float* Q    = path ? Q2     : Q1;
    const float* KV   = path ? KV1    : KV2;
    const float betav = (path ? Beta21 : Beta12)[h];
    float*       O    = path ? O2     : O1;

    const float sc2 = SCALE * LOG2E;
    const float bb2 = betav * LOG2E;

    const int qrow0 = blockIdx.x * (TT * 64) + w * (TT * 16);

    // Q fragments for TT tiles
    unsigned Aq[TT][4][4];
    #pragma unroll
    for (int tt = 0; tt < TT; tt++) {
        const float* qg0 = Q + ((size_t)b * NN + qrow0 + tt*16 + g    ) * CC + h * DD;
        const float* qg8 = Q + ((size_t)b * NN + qrow0 + tt*16 + g + 8) * CC + h * DD;
        #pragma unroll
        for (int kk = 0; kk < 4; kk++) {
            Aq[tt][kk][0] = f2tf32(qg0[kk*8 + t4]);
            Aq[tt][kk][1] = f2tf32(qg8[kk*8 + t4]);
            Aq[tt][kk][2] = f2tf32(qg0[kk*8 + t4 + 4]);
            Aq[tt][kk][3] = f2tf32(qg8[kk*8 + t4 + 4]);
        }
    }

    float o[TT][4][4];
    #pragma unroll
    for (int tt = 0; tt < TT; tt++)
        #pragma unroll
        for (int n = 0; n < 4; n++)
            #pragma unroll
            for (int e = 0; e < 4; e++) o[tt][n][e] = 0.f;
    float l0[TT], l8[TT];
    #pragma unroll
    for (int tt = 0; tt < TT; tt++) { l0[tt] = 0.f; l8[tt] = 0.f; }

    const float* kvb = KV + ((size_t)b * NN) * KVLD + h * DD;

    auto stage = [&](int t, int buf) {
        #pragma unroll
        for (int it = 0; it < 4; it++) {
            int idx = it * 128 + tid;          // 0..511
            int row = idx >> 3, dd = idx & 7;
            const float* src = kvb + (size_t)(t * BC + row) * KVLD + dd * 4;
            cp16(sptr(&Ks[buf][row][dd*4]), src);
            // permuted V slot: pi(c) = (c&1) ? (c>>1)+4 : (c>>1)
            int c = row & 7;
            int vrow = (row & ~7) | ((c & 1) ? (c >> 1) + 4 : (c >> 1));
            cp16(sptr(&Vs[buf][vrow][dd*4]), src + 256);
        }
        CP_COMMIT();
    };

    stage(0, 0);

    for (int t = 0; t < NN / BC; t++) {
        const int buf = t & 1;
        if (t + 1 < NN / BC) { stage(t + 1, buf ^ 1); CP_WAIT(1); }
        else                 { CP_WAIT(0); }
        __syncthreads();

        #pragma unroll
        for (int j = 0; j < 8; j++) {
            // S = Q @ K_j^T for all q-tiles
            float s[TT][4];
            #pragma unroll
            for (int tt = 0; tt < TT; tt++)
                s[tt][0] = s[tt][1] = s[tt][2] = s[tt][3] = 0.f;
            #pragma unroll
            for (int kk = 0; kk < 4; kk++) {
                unsigned kb0 = __float_as_uint(Ks[buf][j*8 + g][kk*8 + t4]);
                unsigned kb1 = __float_as_uint(Ks[buf][j*8 + g][kk*8 + t4 + 4]);
                #pragma unroll
                for (int tt = 0; tt < TT; tt++)
                    mma_tf32(s[tt][0], s[tt][1], s[tt][2], s[tt][3],
                             Aq[tt][kk][0], Aq[tt][kk][1], Aq[tt][kk][2], Aq[tt][kk][3],
                             kb0, kb1);
            }
            // softmax (exp-immediate); results form the PV A-fragment directly
            unsigned a[TT][4];
            #pragma unroll
            for (int tt = 0; tt < TT; tt++) {
                float p0 = exp2f(s[tt][0] * sc2 + bb2);   // row g,   S-col 2t4   -> kdim t4
                float p1 = exp2f(s[tt][1] * sc2 + bb2);   // row g,   S-col 2t4+1 -> kdim t4+4
                float p2 = exp2f(s[tt][2] * sc2 + bb2);   // row g+8, S-col 2t4   -> kdim t4
                float p3 = exp2f(s[tt][3] * sc2 + bb2);   // row g+8, S-col 2t4+1 -> kdim t4+4
                l0[tt] += p0 + p1;
                l8[tt] += p2 + p3;
                a[tt][0] = __float_as_uint(p0);
                a[tt][1] = __float_as_uint(p2);
                a[tt][2] = __float_as_uint(p1);
                a[tt][3] = __float_as_uint(p3);
            }
            // O += P_j @ V_j  (V rows already permuted at staging)
            #pragma unroll
            for (int n = 0; n < 4; n++) {
                unsigned vb0 = __float_as_uint(Vs[buf][j*8 + t4    ][n*8 + g]);
                unsigned vb1 = __float_as_uint(Vs[buf][j*8 + t4 + 4][n*8 + g]);
                #pragma unroll
                for (int tt = 0; tt < TT; tt++)
                    mma_tf32(o[tt][n][0], o[tt][n][1], o[tt][n][2], o[tt][n][3],
                             a[tt][0], a[tt][1], a[tt][2], a[tt][3], vb0, vb1);
            }
        }
        __syncthreads();
    }

    // reduce row sums and store all tiles
    #pragma unroll
    for (int tt = 0; tt < TT; tt++) {
        l0[tt] += __shfl_xor_sync(0xffffffffu, l0[tt], 1);
        l0[tt] += __shfl_xor_sync(0xffffffffu, l0[tt], 2);
        l8[tt] += __shfl_xor_sync(0xffffffffu, l8[tt], 1);
        l8[tt] += __shfl_xor_sync(0xffffffffu, l8[tt], 2);
        const float inv0 = 1.f / l0[tt];
        const float inv8 = 1.f / l8[tt];
        float* og0 = O + ((size_t)b * NN + qrow0 + tt*16 + g    ) * CC + h * DD;
        float* og8 = O + ((size_t)b * NN + qrow0 + tt*16 + g + 8) * CC + h * DD;
        #pragma unroll
        for (int n = 0; n < 4; n++) {
            *(float2*)&og0[n*8 + 2*t4] = make_float2(o[tt][n][0]*inv0, o[tt][n][1]*inv0);
            *(float2*)&og8[n*8 + 2*t4] = make_float2(o[tt][n][2]*inv8, o[tt][n][3]*inv8);
        }
    }
}

// ---------------------------------------------------------------------------
// LayerNorm over C=256
// ---------------------------------------------------------------------------
__global__ __launch_bounds__(256) void cp_layernorm(
    const float* __restrict__ Z, const float* __restrict__ g,
    const float* __restrict__ bta, float* __restrict__ Y)
{
    const int row = blockIdx.x;
    const int t = threadIdx.x;
    float v = Z[(size_t)row * CC + t];

    float s = v, q = v * v;
    #pragma unroll
    for (int o = 16; o > 0; o >>= 1) {
        s += __shfl_xor_sync(0xffffffffu, s, o);
        q += __shfl_xor_sync(0xffffffffu, q, o);
    }
    __shared__ float ssum[8], ssq[8];
    if ((t & 31) == 0) { ssum[t >> 5] = s; ssq[t >> 5] = q; }
    __syncthreads();
    __shared__ float smu, sinv;
    if (t == 0) {
        float ts = 0.f, tq = 0.f;
        #pragma unroll
        for (int w = 0; w < 8; w++) { ts += ssum[w]; tq += ssq[w]; }
        float mu = ts * (1.f / CC);
        float var = tq * (1.f / CC) - mu * mu;
        smu = mu;
        sinv = rsqrtf(var + 1e-5f);
    }
    __syncthreads();
    Y[(size_t)row * CC + t] = (v - smu) * sinv * g[t] + bta[t];
}

// ---------------------------------------------------------------------------
// Bilinear upsample x2
// ---------------------------------------------------------------------------
__global__ __launch_bounds__(256) void cp_upsample(
    const float* __restrict__ Y, float* __restrict__ out)
{
    int idx = blockIdx.x * blockDim.x + threadIdx.x;
    if (idx >= OUT_PER_PATH) return;
    int ox = idx % 96;
    int oy = (idx / 96) % 96;
    int c  = (idx / (96 * 96)) % CC;
    int b  = idx / (96 * 96 * CC);

    float sx = ox * 0.5f - 0.25f;
    float sy = oy * 0.5f - 0.25f;
    int x0 = (int)floorf(sx), y0 = (int)floorf(sy);
    float wx = sx - (float)x0, wy = sy - (float)y0;
    int x0c = max(x0, 0), x1c = min(x0 + 1, HDS - 1);
    int y0c = max(y0, 0), y1c = min(y0 + 1, HDS - 1);

    const float* Yb = Y + (size_t)b * NN * CC + c;
    float v00 = Yb[(size_t)(y0c * HDS + x0c) * CC];
    float v01 = Yb[(size_t)(y0c * HDS + x1c) * CC];
    float v10 = Yb[(size_t)(y1c * HDS + x0c) * CC];
    float v11 = Yb[(size_t)(y1c * HDS + x1c) * CC];

    out[idx] = (1.f - wy) * ((1.f - wx) * v00 + wx * v01)
             +        wy  * ((1.f - wx) * v10 + wx * v11);
}

// ---------------------------------------------------------------------------
// Launch
// ---------------------------------------------------------------------------
extern "C" void kernel_launch(void* const* d_in, const int* in_sizes, int n_in,
                              void* d_out, int out_size)
{
    const float* x1     = (const float*)d_in[0];
    const float* x2     = (const float*)d_in[1];
    const float* q1_w   = (const float*)d_in[2];
    const float* kv1_w  = (const float*)d_in[3];
    const float* q2_w   = (const float*)d_in[4];
    const float* kv2_w  = (const float*)d_in[5];
    const float* beta12 = (const float*)d_in[6];
    const float* beta21 = (const float*)d_in[7];
    const float* p1_w   = (const float*)d_in[8];
    const float* p1_b   = (const float*)d_in[9];
    const float* p2_w   = (const float*)d_in[10];
    const float* p2_b   = (const float*)d_in[11];
    const float* g1     = (const float*)d_in[12];
    const float* b1     = (const float*)d_in[13];
    const float* g2     = (const float*)d_in[14];
    const float* b2     = (const float*)d_in[15];
    float* out = (float*)d_out;

    float *q1, *kv1, *q2, *kv2, *o1, *o2, *z1, *z2, *y1, *y2;
    cudaGetSymbolAddress((void**)&q1,  g_q1);
    cudaGetSymbolAddress((void**)&kv1, g_kv1);
    cudaGetSymbolAddress((void**)&q2,  g_q2);
    cudaGetSymbolAddress((void**)&kv2, g_kv2);
    cudaGetSymbolAddress((void**)&o1,  g_o1);
    cudaGetSymbolAddress((void**)&o2,  g_o2);
    cudaGetSymbolAddress((void**)&z1,  g_z1);
    cudaGetSymbolAddress((void**)&z2,  g_z2);
    cudaGetSymbolAddress((void**)&y1,  g_y1);
    cudaGetSymbolAddress((void**)&y2,  g_y2);

    // Projections (3xTF32 tensor-core GEMM)
    cp_gemm_tc<<<dim3(CC/128,   ROWS/128), 256>>>(x1, q1_w,  nullptr, q1,  ROWS, CC,   CC, 0);
    cp_gemm_tc<<<dim3(KVLD/128, ROWS/128), 256>>>(x1, kv1_w, nullptr, kv1, ROWS, KVLD, CC, 0);
    cp_gemm_tc<<<dim3(CC/128,   ROWS/128), 256>>>(x2, q2_w,  nullptr, q2,  ROWS, CC,   CC, 0);
    cp_gemm_tc<<<dim3(KVLD/128, ROWS/128), 256>>>(x2, kv2_w, nullptr, kv2, ROWS, KVLD, CC, 0);

    // Cross attention on tensor cores (256 queries/block, no P round-trip)
    cp_flash_tc<<<dim3(NN/256, HH, BB*2), 128>>>(q1, kv2, beta12, o1,
                                                 q2, kv1, beta21, o2);

    // Output projection + bias + relu
    cp_gemm_tc<<<dim3(CC/128, ROWS/128), 256>>>(o1, p1_w, p1_b, z1, ROWS, CC, CC, 1);
    cp_gemm_tc<<<dim3(CC/128, ROWS/128), 256>>>(o2, p2_w, p2_b, z2, ROWS, CC, CC, 1);

    // LayerNorm
    cp_layernorm<<<ROWS, 256>>>(z1, g1, b1, y1);
    cp_layernorm<<<ROWS, 256>>>(z2, g2, b2, y2);

    // Bilinear upsample x2 -> output
    int ublocks = (OUT_PER_PATH + 255) / 256;
    cp_upsample<<<ublocks, 256>>>(y1, out);
    cp_upsample<<<ublocks, 256>>>(y2, out + OUT_PER_PATH);
}